// round 4
// baseline (speedup 1.0000x reference)
#include <cuda_runtime.h>
#include <math.h>

#define B_SZ   2
#define L_SZ   1024
#define DM     1024
#define DI     2048
#define DS     16
#define DTR    64
#define DCONV  4
#define BL     (B_SZ * L_SZ)   // 2048 rows

// ---------------- scratch (static device globals; no allocation) ----------------
__device__ float g_xn  [BL * DM];        //  8 MB
__device__ float g_xz  [BL * 2 * DI];    // 32 MB
__device__ float g_xc  [BL * DI];        // 16 MB
__device__ float g_xdbl[BL * 96];        // 0.75 MB
__device__ float g_dt  [BL * DI];        // 16 MB
__device__ float g_y   [BL * DI];        // 16 MB

// ---------------- LayerNorm ----------------
__global__ void ln_kernel(const float* __restrict__ x, const float* __restrict__ g,
                          const float* __restrict__ b, float* __restrict__ out)
{
    int row = blockIdx.x;                 // 0..2047
    const float* xr = x + row * DM;
    float* orow = out + row * DM;
    int t = threadIdx.x;                  // 256 threads
    float s = 0.f, s2 = 0.f;
    for (int i = t; i < DM; i += 256) { float v = xr[i]; s += v; s2 += v * v; }
    __shared__ float sh[20];
    #pragma unroll
    for (int o = 16; o > 0; o >>= 1) {
        s  += __shfl_xor_sync(0xffffffffu, s,  o);
        s2 += __shfl_xor_sync(0xffffffffu, s2, o);
    }
    int wid = t >> 5, lid = t & 31;
    if (lid == 0) { sh[wid] = s; sh[8 + wid] = s2; }
    __syncthreads();
    if (t == 0) {
        float a = 0.f, c = 0.f;
        for (int w = 0; w < 8; w++) { a += sh[w]; c += sh[8 + w]; }
        float mu = a / DM;
        float var = c / DM - mu * mu;
        sh[16] = mu; sh[17] = rsqrtf(var + 1e-5f);
    }
    __syncthreads();
    float mu = sh[16], rs = sh[17];
    for (int i = t; i < DM; i += 256)
        orow[i] = (xr[i] - mu) * rs * g[i] + b[i];
}

// ---------------- generic NT GEMM: C[M,N] = A[M,K] * W[N,K]^T (+bias, epilogue) ----
// EPI: 0 = plain (+bias), 1 = softplus(+bias), 2 = +bias + residual add
template<int EPI>
__global__ void __launch_bounds__(256)
gemm_nt(const float* __restrict__ A, int lda,
        const float* __restrict__ W,          // [N, K] row-major
        const float* __restrict__ bias,       // [N] or nullptr
        const float* __restrict__ res,        // [M, N] or nullptr (EPI==2)
        float* __restrict__ C, int ldc,
        int M, int N, int K)
{
    const int BM = 128, BN = 128, BK = 8;
    __shared__ float As[BK][BM];
    __shared__ float Bs[BK][BN];
    int bm = blockIdx.y * BM, bn = blockIdx.x * BN;
    int t  = threadIdx.x;
    int lr = t >> 1;            // 0..127 (tile row)
    int ls = (t & 1) * 4;       // 0 or 4 (k segment)
    int ty = t >> 4, tx = t & 15;
    int row0 = ty * 8, col0 = tx * 8;

    float acc[8][8];
    #pragma unroll
    for (int i = 0; i < 8; i++)
        #pragma unroll
        for (int j = 0; j < 8; j++) acc[i][j] = 0.f;

    for (int k0 = 0; k0 < K; k0 += BK) {
        // A tile (always in-bounds: M,K multiples of tile sizes used)
        float4 av = *(const float4*)(A + (size_t)(bm + lr) * lda + k0 + ls);
        As[ls + 0][lr] = av.x; As[ls + 1][lr] = av.y;
        As[ls + 2][lr] = av.z; As[ls + 3][lr] = av.w;
        // W tile (guard N: GEMM2 has N=96)
        float4 bv = make_float4(0.f, 0.f, 0.f, 0.f);
        if (bn + lr < N)
            bv = *(const float4*)(W + (size_t)(bn + lr) * K + k0 + ls);
        Bs[ls + 0][lr] = bv.x; Bs[ls + 1][lr] = bv.y;
        Bs[ls + 2][lr] = bv.z; Bs[ls + 3][lr] = bv.w;
        __syncthreads();

        #pragma unroll
        for (int kk = 0; kk < BK; kk++) {
            float4 a0 = *(const float4*)&As[kk][row0];
            float4 a1 = *(const float4*)&As[kk][row0 + 4];
            float4 b0 = *(const float4*)&Bs[kk][col0];
            float4 b1 = *(const float4*)&Bs[kk][col0 + 4];
            float ar[8] = {a0.x, a0.y, a0.z, a0.w, a1.x, a1.y, a1.z, a1.w};
            float br[8] = {b0.x, b0.y, b0.z, b0.w, b1.x, b1.y, b1.z, b1.w};
            #pragma unroll
            for (int i = 0; i < 8; i++)
                #pragma unroll
                for (int j = 0; j < 8; j++)
                    acc[i][j] = fmaf(ar[i], br[j], acc[i][j]);
        }
        __syncthreads();
    }

    #pragma unroll
    for (int i = 0; i < 8; i++) {
        int m = bm + row0 + i;
        #pragma unroll
        for (int j = 0; j < 8; j++) {
            int n = bn + col0 + j;
            if (n < N) {
                float v = acc[i][j];
                if (bias) v += bias[n];
                if (EPI == 1) v = (v > 20.f) ? v : log1pf(__expf(v));
                if (EPI == 2) v += res[(size_t)m * N + n];
                C[(size_t)m * ldc + n] = v;
            }
        }
    }
}

// ---------------- depthwise causal conv + SiLU ----------------
__global__ void conv_silu(const float* __restrict__ xz, const float* __restrict__ cw,
                          const float* __restrict__ cb, float* __restrict__ xc)
{
    int idx = blockIdx.x * blockDim.x + threadIdx.x;    // over BL*DI
    if (idx >= BL * DI) return;
    int d  = idx & (DI - 1);
    int bl = idx >> 11;             // / DI
    int l  = bl & (L_SZ - 1);
    float acc = cb[d];
    #pragma unroll
    for (int k = 0; k < DCONV; k++) {
        int li = l - (DCONV - 1) + k;
        if (li >= 0)
            acc = fmaf(xz[(size_t)(bl - (DCONV - 1 - k)) * (2 * DI) + d],
                       cw[d * DCONV + k], acc);
    }
    float sg = 1.f / (1.f + __expf(-acc));
    xc[idx] = acc * sg;
}

// ---------------- selective scan (16 lanes per channel d) ----------------
__global__ void __launch_bounds__(256)
scan_kernel(const float* __restrict__ dt, const float* __restrict__ xc,
            const float* __restrict__ xdbl, const float* __restrict__ A_log,
            const float* __restrict__ Dp, const float* __restrict__ xz,
            float* __restrict__ y)
{
    int t = threadIdx.x;
    int s = t & 15;                 // state index
    int g = t >> 4;                 // group within block (16 groups)
    int d = blockIdx.x * 16 + g;    // channel
    int b = blockIdx.y;
    float a = -__expf(A_log[d * DS + s]);
    float dscale = Dp[d];
    float h = 0.f;
    int base = b * L_SZ;
    for (int l = 0; l < L_SZ; l++) {
        int bl = base + l;
        float dtv = dt[(size_t)bl * DI + d];
        float xcv = xc[(size_t)bl * DI + d];
        float Bv  = xdbl[(size_t)bl * 96 + 64 + s];
        float Cv  = xdbl[(size_t)bl * 96 + 80 + s];
        float dA  = __expf(dtv * a);
        h = fmaf(dA, h, dtv * xcv * Bv);
        float yp = h * Cv;
        yp += __shfl_xor_sync(0xffffffffu, yp, 8);
        yp += __shfl_xor_sync(0xffffffffu, yp, 4);
        yp += __shfl_xor_sync(0xffffffffu, yp, 2);
        yp += __shfl_xor_sync(0xffffffffu, yp, 1);
        if (s == 0) {
            float zv = xz[(size_t)bl * (2 * DI) + DI + d];
            float sz = zv / (1.f + __expf(-zv));
            y[(size_t)bl * DI + d] = (yp + dscale * xcv) * sz;
        }
    }
}

// ---------------- host launcher ----------------
extern "C" void kernel_launch(void* const* d_in, const int* in_sizes, int n_in,
                              void* d_out, int out_size)
{
    const float* x      = (const float*)d_in[0];
    const float* ln_g   = (const float*)d_in[1];
    const float* ln_b   = (const float*)d_in[2];
    const float* W_in   = (const float*)d_in[3];
    const float* b_in   = (const float*)d_in[4];
    const float* conv_w = (const float*)d_in[5];
    const float* conv_b = (const float*)d_in[6];
    const float* W_x    = (const float*)d_in[7];
    const float* W_dt   = (const float*)d_in[8];
    const float* b_dt   = (const float*)d_in[9];
    const float* A_log  = (const float*)d_in[10];
    const float* Dv     = (const float*)d_in[11];
    const float* W_out  = (const float*)d_in[12];
    const float* b_out  = (const float*)d_in[13];
    float* out = (float*)d_out;

    float *xn, *xz, *xc, *xdbl, *dtb, *yb;
    cudaGetSymbolAddress((void**)&xn,   g_xn);
    cudaGetSymbolAddress((void**)&xz,   g_xz);
    cudaGetSymbolAddress((void**)&xc,   g_xc);
    cudaGetSymbolAddress((void**)&xdbl, g_xdbl);
    cudaGetSymbolAddress((void**)&dtb,  g_dt);
    cudaGetSymbolAddress((void**)&yb,   g_y);

    // 1. LayerNorm
    ln_kernel<<<BL, 256>>>(x, ln_g, ln_b, xn);

    // 2. in-projection: xz[2048,4096] = xn[2048,1024] @ W_in^T + b_in
    gemm_nt<0><<<dim3(4096 / 128, BL / 128), 256>>>(
        xn, DM, W_in, b_in, nullptr, xz, 2 * DI, BL, 2 * DI, DM);

    // 3. depthwise conv + SiLU -> xc[2048,2048]
    conv_silu<<<(BL * DI) / 256, 256>>>(xz, conv_w, conv_b, xc);

    // 4. x_dbl[2048,96] = xc @ W_x^T
    gemm_nt<0><<<dim3(1, BL / 128), 256>>>(
        xc, DI, W_x, nullptr, nullptr, xdbl, 96, BL, 96, DI);

    // 5. dt[2048,2048] = softplus(dt_lo @ W_dt^T + b_dt)   (dt_lo = xdbl[:, :64])
    gemm_nt<1><<<dim3(DI / 128, BL / 128), 256>>>(
        xdbl, 96, W_dt, b_dt, nullptr, dtb, DI, BL, DI, DTR);

    // 6. selective scan + skip + gate -> y[2048,2048]
    scan_kernel<<<dim3(DI / 16, B_SZ), 256>>>(dtb, xc, xdbl, A_log, Dv, xz, yb);

    // 7. out-projection + residual: out = y @ W_out^T + b_out + x
    gemm_nt<2><<<dim3(DM / 128, BL / 128), 256>>>(
        yb, DI, W_out, b_out, x, out, DM, BL, DM, DI);
}

// round 7
// speedup vs baseline: 1.5655x; 1.5655x over previous
#include <cuda_runtime.h>
#include <math.h>
#include <stdint.h>

#define B_SZ   2
#define L_SZ   1024
#define DM     1024
#define DI     2048
#define DS     16
#define DTR    64
#define DCONV  4
#define BL     (B_SZ * L_SZ)   // 2048 rows
#define NSPLIT 8               // split-K factor for GEMM2

// ---------------- scratch (static device globals; no allocation) ----------------
__device__ float g_xn  [BL * DM];
__device__ float g_xz  [BL * 2 * DI];
__device__ float g_xc  [BL * DI];
__device__ float g_xdbl[BL * 96];
__device__ float g_x2p [NSPLIT * BL * 96];   // GEMM2 split-K partials
__device__ float g_dt  [BL * DI];
__device__ float g_y   [BL * DI];

// ---------------- fast exp: FMA-only (keeps MUFU pipe free) ----------------
__device__ __forceinline__ float fexp(float x)
{
    x = fminf(fmaxf(x, -87.f), 87.f);
    float y  = fmaf(x, 1.44269504f, 12582912.f);     // round-to-int via magic
    int   n  = __float_as_int(y) - 0x4B400000;
    float nf = y - 12582912.f;
    float f  = fmaf(x, 1.44269504f, -nf);            // frac in [-0.5, 0.5]
    float t  = f * 0.69314718f;
    float p  = fmaf(t, 8.3333333e-3f, 4.1666667e-2f);
    p = fmaf(p, t, 0.16666667f);
    p = fmaf(p, t, 0.5f);
    p = fmaf(p, t, 1.f);
    p = fmaf(p, t, 1.f);
    return p * __int_as_float((n + 127) << 23);
}

__device__ __forceinline__ uint32_t f2tf32(float v)
{
    uint32_t r;
    asm("cvt.rna.tf32.f32 %0, %1;" : "=r"(r) : "f"(v));
    return r;
}

__device__ __forceinline__ void mma_tf32(float* d, const uint32_t* a, const uint32_t* b)
{
    asm volatile(
        "mma.sync.aligned.m16n8k8.row.col.f32.tf32.tf32.f32 "
        "{%0,%1,%2,%3}, {%4,%5,%6,%7}, {%8,%9}, {%0,%1,%2,%3};\n"
        : "+f"(d[0]), "+f"(d[1]), "+f"(d[2]), "+f"(d[3])
        : "r"(a[0]), "r"(a[1]), "r"(a[2]), "r"(a[3]), "r"(b[0]), "r"(b[1]));
}

// ---------------- LayerNorm ----------------
__global__ void ln_kernel(const float* __restrict__ x, const float* __restrict__ g,
                          const float* __restrict__ b, float* __restrict__ out)
{
    int row = blockIdx.x;
    const float* xr = x + row * DM;
    float* orow = out + row * DM;
    int t = threadIdx.x;
    float s = 0.f, s2 = 0.f;
    for (int i = t; i < DM; i += 256) { float v = xr[i]; s += v; s2 += v * v; }
    __shared__ float sh[20];
    #pragma unroll
    for (int o = 16; o > 0; o >>= 1) {
        s  += __shfl_xor_sync(0xffffffffu, s,  o);
        s2 += __shfl_xor_sync(0xffffffffu, s2, o);
    }
    int wid = t >> 5, lid = t & 31;
    if (lid == 0) { sh[wid] = s; sh[8 + wid] = s2; }
    __syncthreads();
    if (t == 0) {
        float a = 0.f, c = 0.f;
        for (int w = 0; w < 8; w++) { a += sh[w]; c += sh[8 + w]; }
        float mu = a / DM;
        float var = c / DM - mu * mu;
        sh[16] = mu; sh[17] = rsqrtf(var + 1e-5f);
    }
    __syncthreads();
    float mu = sh[16], rs = sh[17];
    for (int i = t; i < DM; i += 256)
        orow[i] = (xr[i] - mu) * rs * g[i] + b[i];
}

// ---------------- tf32 tensor-core NT GEMM: C[M,.] = A[M,K]·W[.,K]^T ----------------
// Tile 128x128x16, 8 warps (4 m x 2 n), each warp 32x64 via m16n8k8 atoms.
// Dims must satisfy: M%128==0, Ncols%128==0, K%16==0 (true for GEMM1/5/7).
// EPI: 0 plain(+bias), 1 softplus(+bias), 2 +bias + residual (stride ldc)
template<int EPI>
__global__ void __launch_bounds__(256)
gemm_tf32(const float* __restrict__ A, int lda,
          const float* __restrict__ W,
          const float* __restrict__ bias,
          const float* __restrict__ res,
          float* __restrict__ C, int ldc, int K)
{
    __shared__ uint32_t As[2][16][132];
    __shared__ uint32_t Ws[2][16][132];

    int bm = blockIdx.y * 128, bn = blockIdx.x * 128;
    int t = threadIdx.x;
    int lane = t & 31, wid = t >> 5;
    int gr = lane >> 2, ct = lane & 3;
    int wm = (wid & 3) * 32, wn = (wid >> 2) * 64;

    int r = t >> 1, seg = (t & 1) * 8;
    const float* aptr = A + (size_t)(bm + r) * lda + seg;
    const float* wptr = W + (size_t)(bn + r) * K + seg;

    float acc[2][8][4];
    #pragma unroll
    for (int i = 0; i < 2; i++)
        #pragma unroll
        for (int j = 0; j < 8; j++)
            #pragma unroll
            for (int k = 0; k < 4; k++) acc[i][j][k] = 0.f;

    // stage 0 preload
    {
        float4 a0 = *(const float4*)aptr;
        float4 a1 = *(const float4*)(aptr + 4);
        float4 w0 = *(const float4*)wptr;
        float4 w1 = *(const float4*)(wptr + 4);
        As[0][seg+0][r] = f2tf32(a0.x); As[0][seg+1][r] = f2tf32(a0.y);
        As[0][seg+2][r] = f2tf32(a0.z); As[0][seg+3][r] = f2tf32(a0.w);
        As[0][seg+4][r] = f2tf32(a1.x); As[0][seg+5][r] = f2tf32(a1.y);
        As[0][seg+6][r] = f2tf32(a1.z); As[0][seg+7][r] = f2tf32(a1.w);
        Ws[0][seg+0][r] = f2tf32(w0.x); Ws[0][seg+1][r] = f2tf32(w0.y);
        Ws[0][seg+2][r] = f2tf32(w0.z); Ws[0][seg+3][r] = f2tf32(w0.w);
        Ws[0][seg+4][r] = f2tf32(w1.x); Ws[0][seg+5][r] = f2tf32(w1.y);
        Ws[0][seg+6][r] = f2tf32(w1.z); Ws[0][seg+7][r] = f2tf32(w1.w);
    }
    __syncthreads();

    int nk = K >> 4;
    for (int kt = 0; kt < nk; kt++) {
        int cur = kt & 1;
        float4 a0, a1, w0, w1;
        bool has = (kt + 1 < nk);
        if (has) {
            const float* ap = aptr + ((kt + 1) << 4);
            const float* wp = wptr + ((kt + 1) << 4);
            a0 = *(const float4*)ap;  a1 = *(const float4*)(ap + 4);
            w0 = *(const float4*)wp;  w1 = *(const float4*)(wp + 4);
        }
        #pragma unroll
        for (int ks = 0; ks < 2; ks++) {
            int kk = ks * 8;
            uint32_t af[2][4], bf[8][2];
            #pragma unroll
            for (int mi = 0; mi < 2; mi++) {
                int mr = wm + mi * 16 + gr;
                af[mi][0] = As[cur][kk + ct    ][mr];
                af[mi][1] = As[cur][kk + ct    ][mr + 8];
                af[mi][2] = As[cur][kk + ct + 4][mr];
                af[mi][3] = As[cur][kk + ct + 4][mr + 8];
            }
            #pragma unroll
            for (int ni = 0; ni < 8; ni++) {
                int nc = wn + ni * 8 + gr;
                bf[ni][0] = Ws[cur][kk + ct    ][nc];
                bf[ni][1] = Ws[cur][kk + ct + 4][nc];
            }
            #pragma unroll
            for (int mi = 0; mi < 2; mi++)
                #pragma unroll
                for (int ni = 0; ni < 8; ni++)
                    mma_tf32(acc[mi][ni], af[mi], bf[ni]);
        }
        if (has) {
            int nxt = cur ^ 1;
            As[nxt][seg+0][r] = f2tf32(a0.x); As[nxt][seg+1][r] = f2tf32(a0.y);
            As[nxt][seg+2][r] = f2tf32(a0.z); As[nxt][seg+3][r] = f2tf32(a0.w);
            As[nxt][seg+4][r] = f2tf32(a1.x); As[nxt][seg+5][r] = f2tf32(a1.y);
            As[nxt][seg+6][r] = f2tf32(a1.z); As[nxt][seg+7][r] = f2tf32(a1.w);
            Ws[nxt][seg+0][r] = f2tf32(w0.x); Ws[nxt][seg+1][r] = f2tf32(w0.y);
            Ws[nxt][seg+2][r] = f2tf32(w0.z); Ws[nxt][seg+3][r] = f2tf32(w0.w);
            Ws[nxt][seg+4][r] = f2tf32(w1.x); Ws[nxt][seg+5][r] = f2tf32(w1.y);
            Ws[nxt][seg+6][r] = f2tf32(w1.z); Ws[nxt][seg+7][r] = f2tf32(w1.w);
        }
        __syncthreads();
    }

    // epilogue: c0:(gr,2ct) c1:(gr,2ct+1) c2:(gr+8,2ct) c3:(gr+8,2ct+1)
    #pragma unroll
    for (int mi = 0; mi < 2; mi++) {
        #pragma unroll
        for (int half = 0; half < 2; half++) {
            int row = bm + wm + mi * 16 + gr + half * 8;
            #pragma unroll
            for (int ni = 0; ni < 8; ni++) {
                int col = bn + wn + ni * 8 + ct * 2;
                float v0 = acc[mi][ni][half * 2 + 0];
                float v1 = acc[mi][ni][half * 2 + 1];
                if (bias) { v0 += bias[col]; v1 += bias[col + 1]; }
                if (EPI == 1) {
                    v0 = (v0 > 20.f) ? v0 : __logf(1.f + fexp(v0));
                    v1 = (v1 > 20.f) ? v1 : __logf(1.f + fexp(v1));
                }
                if (EPI == 2) {
                    const float* rr = res + (size_t)row * ldc;
                    v0 += rr[col]; v1 += rr[col + 1];
                }
                *(float2*)(C + (size_t)row * ldc + col) = make_float2(v0, v1);
            }
        }
    }
}

// ---------------- GEMM2 split-K (M=2048, N=96, K=2048): partials, no atomics ----------------
__global__ void __launch_bounds__(256)
gemm2_splitk(const float* __restrict__ A,     // xc [BL, DI]
             const float* __restrict__ W,     // W_x [96, DI]
             float* __restrict__ part)        // [NSPLIT, BL, 96]
{
    const int KC = DI / NSPLIT;   // 256
    __shared__ float As[16][68];
    __shared__ float Ws[16][100];
    int bm = blockIdx.x * 64;
    int ks = blockIdx.y;
    int k0 = ks * KC;
    int t = threadIdx.x;
    int tr = t >> 4, tc = t & 15;

    float acc[4][6];
    #pragma unroll
    for (int i = 0; i < 4; i++)
        #pragma unroll
        for (int j = 0; j < 6; j++) acc[i][j] = 0.f;

    for (int kk = 0; kk < KC; kk += 16) {
        int arow = t >> 2, aseg = (t & 3) * 4;
        float4 av = *(const float4*)(A + (size_t)(bm + arow) * DI + k0 + kk + aseg);
        As[aseg+0][arow] = av.x; As[aseg+1][arow] = av.y;
        As[aseg+2][arow] = av.z; As[aseg+3][arow] = av.w;
        #pragma unroll
        for (int p = 0; p < 2; p++) {
            int idx = t + p * 256;
            if (idx < 384) {
                int wrow = idx >> 2, wseg = (idx & 3) * 4;
                float4 wv = *(const float4*)(W + (size_t)wrow * DI + k0 + kk + wseg);
                Ws[wseg+0][wrow] = wv.x; Ws[wseg+1][wrow] = wv.y;
                Ws[wseg+2][wrow] = wv.z; Ws[wseg+3][wrow] = wv.w;
            }
        }
        __syncthreads();
        #pragma unroll
        for (int k = 0; k < 16; k++) {
            float ar[4], wr[6];
            #pragma unroll
            for (int i = 0; i < 4; i++) ar[i] = As[k][tr * 4 + i];
            #pragma unroll
            for (int j = 0; j < 6; j++) wr[j] = Ws[k][tc * 6 + j];
            #pragma unroll
            for (int i = 0; i < 4; i++)
                #pragma unroll
                for (int j = 0; j < 6; j++)
                    acc[i][j] = fmaf(ar[i], wr[j], acc[i][j]);
        }
        __syncthreads();
    }
    #pragma unroll
    for (int i = 0; i < 4; i++)
        #pragma unroll
        for (int j = 0; j < 6; j++)
            part[((size_t)ks * BL + bm + tr * 4 + i) * 96 + tc * 6 + j] = acc[i][j];
}

__global__ void reduce_split(const float* __restrict__ p, float* __restrict__ o)
{
    int i = blockIdx.x * 256 + threadIdx.x;
    if (i < BL * 96) {
        float s = 0.f;
        #pragma unroll
        for (int k = 0; k < NSPLIT; k++) s += p[(size_t)k * BL * 96 + i];
        o[i] = s;
    }
}

// ---------------- depthwise causal conv + SiLU ----------------
__global__ void conv_silu(const float* __restrict__ xz, const float* __restrict__ cw,
                          const float* __restrict__ cb, float* __restrict__ xc)
{
    int idx = blockIdx.x * blockDim.x + threadIdx.x;
    if (idx >= BL * DI) return;
    int d  = idx & (DI - 1);
    int bl = idx >> 11;
    int l  = bl & (L_SZ - 1);
    float acc = cb[d];
    #pragma unroll
    for (int k = 0; k < DCONV; k++) {
        int li = l - (DCONV - 1) + k;
        if (li >= 0)
            acc = fmaf(xz[(size_t)(bl - (DCONV - 1 - k)) * (2 * DI) + d],
                       cw[d * DCONV + k], acc);
    }
    float sg = 1.f / (1.f + fexp(-acc));
    xc[idx] = acc * sg;
}

// ---------------- selective scan (16 lanes per channel d) ----------------
__global__ void __launch_bounds__(256)
scan_kernel(const float* __restrict__ dt, const float* __restrict__ xc,
            const float* __restrict__ xdbl, const float* __restrict__ A_log,
            const float* __restrict__ Dp, const float* __restrict__ xz,
            float* __restrict__ y)
{
    int t = threadIdx.x;
    int s = t & 15;
    int g = t >> 4;
    int d = blockIdx.x * 16 + g;
    int b = blockIdx.y;
    float a = -__expf(A_log[d * DS + s]);
    float dscale = Dp[d];
    float h = 0.f;
    int base = b * L_SZ;
    for (int l = 0; l < L_SZ; l++) {
        int bl = base + l;
        float dtv = dt[(size_t)bl * DI + d];
        float xcv = xc[(size_t)bl * DI + d];
        float Bv  = xdbl[(size_t)bl * 96 + 64 + s];
        float Cv  = xdbl[(size_t)bl * 96 + 80 + s];
        float dA  = fexp(dtv * a);
        h = fmaf(dA, h, dtv * xcv * Bv);
        float yp = h * Cv;
        yp += __shfl_xor_sync(0xffffffffu, yp, 8);
        yp += __shfl_xor_sync(0xffffffffu, yp, 4);
        yp += __shfl_xor_sync(0xffffffffu, yp, 2);
        yp += __shfl_xor_sync(0xffffffffu, yp, 1);
        if (s == 0) {
            float zv = xz[(size_t)bl * (2 * DI) + DI + d];
            float sz = zv / (1.f + fexp(-zv));
            y[(size_t)bl * DI + d] = (yp + dscale * xcv) * sz;
        }
    }
}

// ---------------- host launcher ----------------
extern "C" void kernel_launch(void* const* d_in, const int* in_sizes, int n_in,
                              void* d_out, int out_size)
{
    const float* x      = (const float*)d_in[0];
    const float* ln_g   = (const float*)d_in[1];
    const float* ln_b   = (const float*)d_in[2];
    const float* W_in   = (const float*)d_in[3];
    const float* b_in   = (const float*)d_in[4];
    const float* conv_w = (const float*)d_in[5];
    const float* conv_b = (const float*)d_in[6];
    const float* W_x    = (const float*)d_in[7];
    const float* W_dt   = (const float*)d_in[8];
    const float* b_dt   = (const float*)d_in[9];
    const float* A_log  = (const float*)d_in[10];
    const float* Dv     = (const float*)d_in[11];
    const float* W_out  = (const float*)d_in[12];
    const float* b_out  = (const float*)d_in[13];
    float* out = (float*)d_out;

    float *xn, *xz, *xc, *xdbl, *x2p, *dtb, *yb;
    cudaGetSymbolAddress((void**)&xn,   g_xn);
    cudaGetSymbolAddress((void**)&xz,   g_xz);
    cudaGetSymbolAddress((void**)&xc,   g_xc);
    cudaGetSymbolAddress((void**)&xdbl, g_xdbl);
    cudaGetSymbolAddress((void**)&x2p,  g_x2p);
    cudaGetSymbolAddress((void**)&dtb,  g_dt);
    cudaGetSymbolAddress((void**)&yb,   g_y);

    // 1. LayerNorm
    ln_kernel<<<BL, 256>>>(x, ln_g, ln_b, xn);

    // 2. in-projection (tf32 TC): xz[2048,4096] = xn @ W_in^T + b_in
    gemm_tf32<0><<<dim3(4096 / 128, BL / 128), 256>>>(
        xn, DM, W_in, b_in, nullptr, xz, 2 * DI, DM);

    // 3. depthwise conv + SiLU
    conv_silu<<<(BL * DI) / 256, 256>>>(xz, conv_w, conv_b, xc);

    // 4. x_dbl = xc @ W_x^T  (split-K, fp32, deterministic reduce)
    gemm2_splitk<<<dim3(BL / 64, NSPLIT), 256>>>(xc, W_x, x2p);
    reduce_split<<<(BL * 96 + 255) / 256, 256>>>(x2p, xdbl);

    // 5. dt = softplus(dt_lo @ W_dt^T + b_dt) (tf32 TC)
    gemm_tf32<1><<<dim3(DI / 128, BL / 128), 256>>>(
        xdbl, 96, W_dt, b_dt, nullptr, dtb, DI, DTR);

    // 6. selective scan + skip + gate
    scan_kernel<<<dim3(DI / 16, B_SZ), 256>>>(dtb, xc, xdbl, A_log, Dv, xz, yb);

    // 7. out-projection + residual (tf32 TC)
    gemm_tf32<2><<<dim3(DM / 128, BL / 128), 256>>>(
        yb, DI, W_out, b_out, x, out, DM, DI);
}

// round 8
// speedup vs baseline: 2.8458x; 1.8179x over previous
#include <cuda_runtime.h>
#include <math.h>
#include <stdint.h>

#define B_SZ   2
#define L_SZ   1024
#define DM     1024
#define DI     2048
#define DS     16
#define DTR    64
#define DCONV  4
#define BL     (B_SZ * L_SZ)   // 2048 rows
#define NSPLIT 8               // split-K factor for GEMM2
#define NCH    4               // scan chunks per sequence
#define LC     (L_SZ / NCH)    // 256 steps per chunk

// ---------------- scratch (static device globals; no allocation) ----------------
__device__ float g_xn  [BL * DM];
__device__ float g_xz  [BL * 2 * DI];
__device__ float g_xc  [BL * DI];
__device__ float g_xdbl[BL * 96];
__device__ float g_x2p [NSPLIT * BL * 96];
__device__ float g_dt  [BL * DI];
__device__ float g_y   [BL * DI];
__device__ float g_hq  [B_SZ * NCH * DI * DS];   // chunk q (h with h0=0)
__device__ float g_hP  [B_SZ * NCH * DI * DS];   // chunk dA products
__device__ float g_h0  [B_SZ * NCH * DI * DS];   // chunk initial states

// ---------------- fast exp: FMA-only ----------------
__device__ __forceinline__ float fexp(float x)
{
    x = fminf(fmaxf(x, -87.f), 87.f);
    float y  = fmaf(x, 1.44269504f, 12582912.f);
    int   n  = __float_as_int(y) - 0x4B400000;
    float nf = y - 12582912.f;
    float f  = fmaf(x, 1.44269504f, -nf);
    float t  = f * 0.69314718f;
    float p  = fmaf(t, 8.3333333e-3f, 4.1666667e-2f);
    p = fmaf(p, t, 0.16666667f);
    p = fmaf(p, t, 0.5f);
    p = fmaf(p, t, 1.f);
    p = fmaf(p, t, 1.f);
    return p * __int_as_float((n + 127) << 23);
}

__device__ __forceinline__ uint32_t f2tf32(float v)
{
    uint32_t r;
    asm("cvt.rna.tf32.f32 %0, %1;" : "=r"(r) : "f"(v));
    return r;
}

__device__ __forceinline__ void mma_tf32(float* d, const uint32_t* a, const uint32_t* b)
{
    asm volatile(
        "mma.sync.aligned.m16n8k8.row.col.f32.tf32.tf32.f32 "
        "{%0,%1,%2,%3}, {%4,%5,%6,%7}, {%8,%9}, {%0,%1,%2,%3};\n"
        : "+f"(d[0]), "+f"(d[1]), "+f"(d[2]), "+f"(d[3])
        : "r"(a[0]), "r"(a[1]), "r"(a[2]), "r"(a[3]), "r"(b[0]), "r"(b[1]));
}

// ---------------- LayerNorm ----------------
__global__ void ln_kernel(const float* __restrict__ x, const float* __restrict__ g,
                          const float* __restrict__ b, float* __restrict__ out)
{
    int row = blockIdx.x;
    const float* xr = x + row * DM;
    float* orow = out + row * DM;
    int t = threadIdx.x;
    float s = 0.f, s2 = 0.f;
    for (int i = t; i < DM; i += 256) { float v = xr[i]; s += v; s2 += v * v; }
    __shared__ float sh[20];
    #pragma unroll
    for (int o = 16; o > 0; o >>= 1) {
        s  += __shfl_xor_sync(0xffffffffu, s,  o);
        s2 += __shfl_xor_sync(0xffffffffu, s2, o);
    }
    int wid = t >> 5, lid = t & 31;
    if (lid == 0) { sh[wid] = s; sh[8 + wid] = s2; }
    __syncthreads();
    if (t == 0) {
        float a = 0.f, c = 0.f;
        for (int w = 0; w < 8; w++) { a += sh[w]; c += sh[8 + w]; }
        float mu = a / DM;
        float var = c / DM - mu * mu;
        sh[16] = mu; sh[17] = rsqrtf(var + 1e-5f);
    }
    __syncthreads();
    float mu = sh[16], rs = sh[17];
    for (int i = t; i < DM; i += 256)
        orow[i] = (xr[i] - mu) * rs * g[i] + b[i];
}

// ---------------- tf32 tensor-core NT GEMM (128x128x16 tile, 8 warps) ----------------
template<int EPI>
__global__ void __launch_bounds__(256)
gemm_tf32(const float* __restrict__ A, int lda,
          const float* __restrict__ W,
          const float* __restrict__ bias,
          const float* __restrict__ res,
          float* __restrict__ C, int ldc, int K)
{
    __shared__ uint32_t As[2][16][132];
    __shared__ uint32_t Ws[2][16][132];

    int bm = blockIdx.y * 128, bn = blockIdx.x * 128;
    int t = threadIdx.x;
    int lane = t & 31, wid = t >> 5;
    int gr = lane >> 2, ct = lane & 3;
    int wm = (wid & 3) * 32, wn = (wid >> 2) * 64;

    int r = t >> 1, seg = (t & 1) * 8;
    const float* aptr = A + (size_t)(bm + r) * lda + seg;
    const float* wptr = W + (size_t)(bn + r) * K + seg;

    float acc[2][8][4];
    #pragma unroll
    for (int i = 0; i < 2; i++)
        #pragma unroll
        for (int j = 0; j < 8; j++)
            #pragma unroll
            for (int k = 0; k < 4; k++) acc[i][j][k] = 0.f;

    {
        float4 a0 = *(const float4*)aptr;
        float4 a1 = *(const float4*)(aptr + 4);
        float4 w0 = *(const float4*)wptr;
        float4 w1 = *(const float4*)(wptr + 4);
        As[0][seg+0][r] = f2tf32(a0.x); As[0][seg+1][r] = f2tf32(a0.y);
        As[0][seg+2][r] = f2tf32(a0.z); As[0][seg+3][r] = f2tf32(a0.w);
        As[0][seg+4][r] = f2tf32(a1.x); As[0][seg+5][r] = f2tf32(a1.y);
        As[0][seg+6][r] = f2tf32(a1.z); As[0][seg+7][r] = f2tf32(a1.w);
        Ws[0][seg+0][r] = f2tf32(w0.x); Ws[0][seg+1][r] = f2tf32(w0.y);
        Ws[0][seg+2][r] = f2tf32(w0.z); Ws[0][seg+3][r] = f2tf32(w0.w);
        Ws[0][seg+4][r] = f2tf32(w1.x); Ws[0][seg+5][r] = f2tf32(w1.y);
        Ws[0][seg+6][r] = f2tf32(w1.z); Ws[0][seg+7][r] = f2tf32(w1.w);
    }
    __syncthreads();

    int nk = K >> 4;
    for (int kt = 0; kt < nk; kt++) {
        int cur = kt & 1;
        float4 a0, a1, w0, w1;
        bool has = (kt + 1 < nk);
        if (has) {
            const float* ap = aptr + ((kt + 1) << 4);
            const float* wp = wptr + ((kt + 1) << 4);
            a0 = *(const float4*)ap;  a1 = *(const float4*)(ap + 4);
            w0 = *(const float4*)wp;  w1 = *(const float4*)(wp + 4);
        }
        #pragma unroll
        for (int ks = 0; ks < 2; ks++) {
            int kk = ks * 8;
            uint32_t af[2][4], bf[8][2];
            #pragma unroll
            for (int mi = 0; mi < 2; mi++) {
                int mr = wm + mi * 16 + gr;
                af[mi][0] = As[cur][kk + ct    ][mr];
                af[mi][1] = As[cur][kk + ct    ][mr + 8];
                af[mi][2] = As[cur][kk + ct + 4][mr];
                af[mi][3] = As[cur][kk + ct + 4][mr + 8];
            }
            #pragma unroll
            for (int ni = 0; ni < 8; ni++) {
                int nc = wn + ni * 8 + gr;
                bf[ni][0] = Ws[cur][kk + ct    ][nc];
                bf[ni][1] = Ws[cur][kk + ct + 4][nc];
            }
            #pragma unroll
            for (int mi = 0; mi < 2; mi++)
                #pragma unroll
                for (int ni = 0; ni < 8; ni++)
                    mma_tf32(acc[mi][ni], af[mi], bf[ni]);
        }
        if (has) {
            int nxt = cur ^ 1;
            As[nxt][seg+0][r] = f2tf32(a0.x); As[nxt][seg+1][r] = f2tf32(a0.y);
            As[nxt][seg+2][r] = f2tf32(a0.z); As[nxt][seg+3][r] = f2tf32(a0.w);
            As[nxt][seg+4][r] = f2tf32(a1.x); As[nxt][seg+5][r] = f2tf32(a1.y);
            As[nxt][seg+6][r] = f2tf32(a1.z); As[nxt][seg+7][r] = f2tf32(a1.w);
            Ws[nxt][seg+0][r] = f2tf32(w0.x); Ws[nxt][seg+1][r] = f2tf32(w0.y);
            Ws[nxt][seg+2][r] = f2tf32(w0.z); Ws[nxt][seg+3][r] = f2tf32(w0.w);
            Ws[nxt][seg+4][r] = f2tf32(w1.x); Ws[nxt][seg+5][r] = f2tf32(w1.y);
            Ws[nxt][seg+6][r] = f2tf32(w1.z); Ws[nxt][seg+7][r] = f2tf32(w1.w);
        }
        __syncthreads();
    }

    #pragma unroll
    for (int mi = 0; mi < 2; mi++) {
        #pragma unroll
        for (int half = 0; half < 2; half++) {
            int row = bm + wm + mi * 16 + gr + half * 8;
            #pragma unroll
            for (int ni = 0; ni < 8; ni++) {
                int col = bn + wn + ni * 8 + ct * 2;
                float v0 = acc[mi][ni][half * 2 + 0];
                float v1 = acc[mi][ni][half * 2 + 1];
                if (bias) { v0 += bias[col]; v1 += bias[col + 1]; }
                if (EPI == 1) {
                    v0 = (v0 > 20.f) ? v0 : __logf(1.f + fexp(v0));
                    v1 = (v1 > 20.f) ? v1 : __logf(1.f + fexp(v1));
                }
                if (EPI == 2) {
                    const float* rr = res + (size_t)row * ldc;
                    v0 += rr[col]; v1 += rr[col + 1];
                }
                *(float2*)(C + (size_t)row * ldc + col) = make_float2(v0, v1);
            }
        }
    }
}

// ---------------- GEMM2 split-K ----------------
__global__ void __launch_bounds__(256)
gemm2_splitk(const float* __restrict__ A,
             const float* __restrict__ W,
             float* __restrict__ part)
{
    const int KC = DI / NSPLIT;
    __shared__ float As[16][68];
    __shared__ float Ws[16][100];
    int bm = blockIdx.x * 64;
    int ks = blockIdx.y;
    int k0 = ks * KC;
    int t = threadIdx.x;
    int tr = t >> 4, tc = t & 15;

    float acc[4][6];
    #pragma unroll
    for (int i = 0; i < 4; i++)
        #pragma unroll
        for (int j = 0; j < 6; j++) acc[i][j] = 0.f;

    for (int kk = 0; kk < KC; kk += 16) {
        int arow = t >> 2, aseg = (t & 3) * 4;
        float4 av = *(const float4*)(A + (size_t)(bm + arow) * DI + k0 + kk + aseg);
        As[aseg+0][arow] = av.x; As[aseg+1][arow] = av.y;
        As[aseg+2][arow] = av.z; As[aseg+3][arow] = av.w;
        #pragma unroll
        for (int p = 0; p < 2; p++) {
            int idx = t + p * 256;
            if (idx < 384) {
                int wrow = idx >> 2, wseg = (idx & 3) * 4;
                float4 wv = *(const float4*)(W + (size_t)wrow * DI + k0 + kk + wseg);
                Ws[wseg+0][wrow] = wv.x; Ws[wseg+1][wrow] = wv.y;
                Ws[wseg+2][wrow] = wv.z; Ws[wseg+3][wrow] = wv.w;
            }
        }
        __syncthreads();
        #pragma unroll
        for (int k = 0; k < 16; k++) {
            float ar[4], wr[6];
            #pragma unroll
            for (int i = 0; i < 4; i++) ar[i] = As[k][tr * 4 + i];
            #pragma unroll
            for (int j = 0; j < 6; j++) wr[j] = Ws[k][tc * 6 + j];
            #pragma unroll
            for (int i = 0; i < 4; i++)
                #pragma unroll
                for (int j = 0; j < 6; j++)
                    acc[i][j] = fmaf(ar[i], wr[j], acc[i][j]);
        }
        __syncthreads();
    }
    #pragma unroll
    for (int i = 0; i < 4; i++)
        #pragma unroll
        for (int j = 0; j < 6; j++)
            part[((size_t)ks * BL + bm + tr * 4 + i) * 96 + tc * 6 + j] = acc[i][j];
}

__global__ void reduce_split(const float* __restrict__ p, float* __restrict__ o)
{
    int i = blockIdx.x * 256 + threadIdx.x;
    if (i < BL * 96) {
        float s = 0.f;
        #pragma unroll
        for (int k = 0; k < NSPLIT; k++) s += p[(size_t)k * BL * 96 + i];
        o[i] = s;
    }
}

// ---------------- depthwise causal conv + SiLU ----------------
__global__ void conv_silu(const float* __restrict__ xz, const float* __restrict__ cw,
                          const float* __restrict__ cb, float* __restrict__ xc)
{
    int idx = blockIdx.x * blockDim.x + threadIdx.x;
    if (idx >= BL * DI) return;
    int d  = idx & (DI - 1);
    int bl = idx >> 11;
    int l  = bl & (L_SZ - 1);
    float acc = cb[d];
    #pragma unroll
    for (int k = 0; k < DCONV; k++) {
        int li = l - (DCONV - 1) + k;
        if (li >= 0)
            acc = fmaf(xz[(size_t)(bl - (DCONV - 1 - k)) * (2 * DI) + d],
                       cw[d * DCONV + k], acc);
    }
    float sg = 1.f / (1.f + fexp(-acc));
    xc[idx] = acc * sg;
}

// ---------------- scan pass 1: per-chunk (P, q) with h0 = 0 ----------------
// grid: (DI/16, NCH, B_SZ), block 256 (16 groups of 16 states)
__global__ void __launch_bounds__(256)
scan_pass1(const float* __restrict__ dt, const float* __restrict__ xc,
           const float* __restrict__ xdbl, const float* __restrict__ A_log,
           float* __restrict__ hq, float* __restrict__ hP)
{
    int t = threadIdx.x;
    int s = t & 15;
    int g = t >> 4;
    int d = blockIdx.x * 16 + g;
    int c = blockIdx.y;
    int b = blockIdx.z;
    float a = -fexp(A_log[d * DS + s]);
    float h = 0.f, P = 1.f;
    int base = b * L_SZ + c * LC;
    #pragma unroll 4
    for (int l = 0; l < LC; l++) {
        int bl = base + l;
        float dtv = dt[(size_t)bl * DI + d];
        float xcv = xc[(size_t)bl * DI + d];
        float Bv  = xdbl[(size_t)bl * 96 + 64 + s];
        float dA  = fexp(dtv * a);
        h = fmaf(dA, h, dtv * xcv * Bv);
        P *= dA;
    }
    size_t idx = ((size_t)(b * NCH + c) * DI + d) * DS + s;
    hq[idx] = h;
    hP[idx] = P;
}

// ---------------- scan fixup: propagate chunk-initial states ----------------
__global__ void scan_fix(const float* __restrict__ hq, const float* __restrict__ hP,
                         float* __restrict__ h0)
{
    int i = blockIdx.x * 256 + threadIdx.x;       // over B*DI*DS = 65536
    if (i >= B_SZ * DI * DS) return;
    int s = i & 15;
    int d = (i >> 4) & (DI - 1);
    int b = i >> 15;
    float h = 0.f;
    #pragma unroll
    for (int c = 0; c < NCH; c++) {
        size_t idx = ((size_t)(b * NCH + c) * DI + d) * DS + s;
        h0[idx] = h;
        h = fmaf(hP[idx], h, hq[idx]);
    }
}

// ---------------- scan pass 2: re-scan chunks from correct h0, emit y ----------------
__global__ void __launch_bounds__(256)
scan_pass2(const float* __restrict__ dt, const float* __restrict__ xc,
           const float* __restrict__ xdbl, const float* __restrict__ A_log,
           const float* __restrict__ Dp, const float* __restrict__ xz,
           const float* __restrict__ h0, float* __restrict__ y)
{
    int t = threadIdx.x;
    int s = t & 15;
    int g = t >> 4;
    int d = blockIdx.x * 16 + g;
    int c = blockIdx.y;
    int b = blockIdx.z;
    float a = -fexp(A_log[d * DS + s]);
    float dscale = Dp[d];
    float h = h0[((size_t)(b * NCH + c) * DI + d) * DS + s];
    int base = b * L_SZ + c * LC;
    #pragma unroll 2
    for (int l = 0; l < LC; l++) {
        int bl = base + l;
        float dtv = dt[(size_t)bl * DI + d];
        float xcv = xc[(size_t)bl * DI + d];
        float Bv  = xdbl[(size_t)bl * 96 + 64 + s];
        float Cv  = xdbl[(size_t)bl * 96 + 80 + s];
        float dA  = fexp(dtv * a);
        h = fmaf(dA, h, dtv * xcv * Bv);
        float yp = h * Cv;
        yp += __shfl_xor_sync(0xffffffffu, yp, 8);
        yp += __shfl_xor_sync(0xffffffffu, yp, 4);
        yp += __shfl_xor_sync(0xffffffffu, yp, 2);
        yp += __shfl_xor_sync(0xffffffffu, yp, 1);
        if (s == 0) {
            float zv = xz[(size_t)bl * (2 * DI) + DI + d];
            float sz = zv / (1.f + fexp(-zv));
            y[(size_t)bl * DI + d] = (yp + dscale * xcv) * sz;
        }
    }
}

// ---------------- host launcher ----------------
extern "C" void kernel_launch(void* const* d_in, const int* in_sizes, int n_in,
                              void* d_out, int out_size)
{
    const float* x      = (const float*)d_in[0];
    const float* ln_g   = (const float*)d_in[1];
    const float* ln_b   = (const float*)d_in[2];
    const float* W_in   = (const float*)d_in[3];
    const float* b_in   = (const float*)d_in[4];
    const float* conv_w = (const float*)d_in[5];
    const float* conv_b = (const float*)d_in[6];
    const float* W_x    = (const float*)d_in[7];
    const float* W_dt   = (const float*)d_in[8];
    const float* b_dt   = (const float*)d_in[9];
    const float* A_log  = (const float*)d_in[10];
    const float* Dv     = (const float*)d_in[11];
    const float* W_out  = (const float*)d_in[12];
    const float* b_out  = (const float*)d_in[13];
    float* out = (float*)d_out;

    float *xn, *xz, *xc, *xdbl, *x2p, *dtb, *yb, *hq, *hP, *h0;
    cudaGetSymbolAddress((void**)&xn,   g_xn);
    cudaGetSymbolAddress((void**)&xz,   g_xz);
    cudaGetSymbolAddress((void**)&xc,   g_xc);
    cudaGetSymbolAddress((void**)&xdbl, g_xdbl);
    cudaGetSymbolAddress((void**)&x2p,  g_x2p);
    cudaGetSymbolAddress((void**)&dtb,  g_dt);
    cudaGetSymbolAddress((void**)&yb,   g_y);
    cudaGetSymbolAddress((void**)&hq,   g_hq);
    cudaGetSymbolAddress((void**)&hP,   g_hP);
    cudaGetSymbolAddress((void**)&h0,   g_h0);

    // 1. LayerNorm
    ln_kernel<<<BL, 256>>>(x, ln_g, ln_b, xn);

    // 2. in-projection (tf32 TC)
    gemm_tf32<0><<<dim3(4096 / 128, BL / 128), 256>>>(
        xn, DM, W_in, b_in, nullptr, xz, 2 * DI, DM);

    // 3. depthwise conv + SiLU
    conv_silu<<<(BL * DI) / 256, 256>>>(xz, conv_w, conv_b, xc);

    // 4. x_dbl = xc @ W_x^T (split-K)
    gemm2_splitk<<<dim3(BL / 64, NSPLIT), 256>>>(xc, W_x, x2p);
    reduce_split<<<(BL * 96 + 255) / 256, 256>>>(x2p, xdbl);

    // 5. dt = softplus(dt_lo @ W_dt^T + b_dt) (tf32 TC)
    gemm_tf32<1><<<dim3(DI / 128, BL / 128), 256>>>(
        xdbl, 96, W_dt, b_dt, nullptr, dtb, DI, DTR);

    // 6. chunked selective scan (pass1 -> fixup -> pass2)
    scan_pass1<<<dim3(DI / 16, NCH, B_SZ), 256>>>(dtb, xc, xdbl, A_log, hq, hP);
    scan_fix<<<(B_SZ * DI * DS) / 256, 256>>>(hq, hP, h0);
    scan_pass2<<<dim3(DI / 16, NCH, B_SZ), 256>>>(dtb, xc, xdbl, A_log, Dv, xz, h0, yb);

    // 7. out-projection + residual (tf32 TC)
    gemm_tf32<2><<<dim3(DM / 128, BL / 128), 256>>>(
        yb, DI, W_out, b_out, x, out, DM, DI);
}

// round 13
// speedup vs baseline: 3.1918x; 1.1216x over previous
#include <cuda_runtime.h>
#include <math.h>
#include <stdint.h>

#define B_SZ   2
#define L_SZ   1024
#define DM     1024
#define DI     2048
#define DS     16
#define DTR    64
#define DCONV  4
#define BL     (B_SZ * L_SZ)   // 2048 rows
#define NSPLIT 16              // split-K factor for GEMM2
#define NCH    8               // scan chunks per sequence
#define LC     (L_SZ / NCH)    // 128 steps per chunk

#define LDT    20                              // smem row stride (words), 16+4 pad
#define GSM    (4 * 2 * 128 * LDT * 4)         // gemm dynamic smem: 81920 B

// ---------------- scratch (static device globals; no allocation) ----------------
__device__ float g_xn  [BL * DM];
__device__ float g_xz  [BL * 2 * DI];
__device__ float g_xc  [BL * DI];
__device__ float g_xdbl[BL * 96];
__device__ float g_x2p [NSPLIT * BL * 96];
__device__ float g_dt  [BL * DI];
__device__ float g_y   [BL * DI];
__device__ float g_hq  [B_SZ * NCH * DI * DS];
__device__ float g_hP  [B_SZ * NCH * DI * DS];
__device__ float g_h0  [B_SZ * NCH * DI * DS];
__device__ float g_rWin [2 * DI * DM];   // tf32-rounded weights
__device__ float g_rWdt [DI * DTR];
__device__ float g_rWout[DM * DI];

// ---------------- helpers ----------------
__device__ __forceinline__ float fexp(float x)
{
    x = fminf(fmaxf(x, -87.f), 87.f);
    float y  = fmaf(x, 1.44269504f, 12582912.f);
    int   n  = __float_as_int(y) - 0x4B400000;
    float nf = y - 12582912.f;
    float f  = fmaf(x, 1.44269504f, -nf);
    float t  = f * 0.69314718f;
    float p  = fmaf(t, 8.3333333e-3f, 4.1666667e-2f);
    p = fmaf(p, t, 0.16666667f);
    p = fmaf(p, t, 0.5f);
    p = fmaf(p, t, 1.f);
    p = fmaf(p, t, 1.f);
    return p * __int_as_float((n + 127) << 23);
}

__device__ __forceinline__ uint32_t f2tf32(float v)
{
    uint32_t r;
    asm("cvt.rna.tf32.f32 %0, %1;" : "=r"(r) : "f"(v));
    return r;
}
__device__ __forceinline__ float rtf(float v) { return __uint_as_float(f2tf32(v)); }

__device__ __forceinline__ void mma_tf32(float* d, const uint32_t* a, const uint32_t* b)
{
    asm volatile(
        "mma.sync.aligned.m16n8k8.row.col.f32.tf32.tf32.f32 "
        "{%0,%1,%2,%3}, {%4,%5,%6,%7}, {%8,%9}, {%0,%1,%2,%3};\n"
        : "+f"(d[0]), "+f"(d[1]), "+f"(d[2]), "+f"(d[3])
        : "r"(a[0]), "r"(a[1]), "r"(a[2]), "r"(a[3]), "r"(b[0]), "r"(b[1]));
}

__device__ __forceinline__ void cp16(float* smem, const float* g)
{
    uint32_t sa = (uint32_t)__cvta_generic_to_shared(smem);
    asm volatile("cp.async.cg.shared.global [%0], [%1], 16;\n" :: "r"(sa), "l"(g));
}
__device__ __forceinline__ void cp_commit() { asm volatile("cp.async.commit_group;\n"); }
template<int N>
__device__ __forceinline__ void cp_wait() { asm volatile("cp.async.wait_group %0;\n" :: "n"(N)); }

// ---------------- tf32 weight pre-rounding ----------------
__global__ void cvt_tf32(const float* __restrict__ in, float* __restrict__ out, int n4)
{
    int i = blockIdx.x * 256 + threadIdx.x;
    if (i < n4) {
        float4 v = ((const float4*)in)[i];
        v.x = rtf(v.x); v.y = rtf(v.y); v.z = rtf(v.z); v.w = rtf(v.w);
        ((float4*)out)[i] = v;
    }
}

// ---------------- LayerNorm (outputs tf32-rounded xn) ----------------
__global__ void ln_kernel(const float* __restrict__ x, const float* __restrict__ g,
                          const float* __restrict__ b, float* __restrict__ out)
{
    int row = blockIdx.x;
    const float* xr = x + row * DM;
    float* orow = out + row * DM;
    int t = threadIdx.x;
    float s = 0.f, s2 = 0.f;
    for (int i = t; i < DM; i += 256) { float v = xr[i]; s += v; s2 += v * v; }
    __shared__ float sh[20];
    #pragma unroll
    for (int o = 16; o > 0; o >>= 1) {
        s  += __shfl_xor_sync(0xffffffffu, s,  o);
        s2 += __shfl_xor_sync(0xffffffffu, s2, o);
    }
    int wid = t >> 5, lid = t & 31;
    if (lid == 0) { sh[wid] = s; sh[8 + wid] = s2; }
    __syncthreads();
    if (t == 0) {
        float a = 0.f, c = 0.f;
        for (int w = 0; w < 8; w++) { a += sh[w]; c += sh[8 + w]; }
        float mu = a / DM;
        float var = c / DM - mu * mu;
        sh[16] = mu; sh[17] = rsqrtf(var + 1e-5f);
    }
    __syncthreads();
    float mu = sh[16], rs = sh[17];
    for (int i = t; i < DM; i += 256)
        orow[i] = rtf((xr[i] - mu) * rs * g[i] + b[i]);
}

// ---------------- tf32 TC GEMM, 4-stage cp.async pipeline ----------------
// Operands in gmem MUST already be tf32-rounded. Smem layout [stage][row][LDT].
// C[M,.] = A[M,K]·W[.,K]^T. Tile 128x128x16, 8 warps. M%128==0, N%128==0, K%16==0.
template<int EPI>
__global__ void __launch_bounds__(256)
gemm_tf32(const float* __restrict__ A, int lda,
          const float* __restrict__ W,
          const float* __restrict__ bias,
          const float* __restrict__ res,
          float* __restrict__ C, int ldc, int K)
{
    extern __shared__ float smem[];
    float* Abuf = smem;                       // [4][128][LDT]
    float* Wbuf = smem + 4 * 128 * LDT;

    int bm = blockIdx.y * 128, bn = blockIdx.x * 128;
    int t = threadIdx.x;
    int lane = t & 31, wid = t >> 5;
    int gr = lane >> 2, ct = lane & 3;
    int wm = (wid & 3) * 32, wn = (wid >> 2) * 64;

    // two 16B chunks per operand per thread (512 chunks per 128x16 tile)
    int c0 = t * 2, c1 = t * 2 + 1;
    int r0 = c0 >> 2, s0 = (c0 & 3) * 4;
    int r1 = c1 >> 2, s1 = (c1 & 3) * 4;

    float acc[2][8][4];
    #pragma unroll
    for (int i = 0; i < 2; i++)
        #pragma unroll
        for (int j = 0; j < 8; j++)
            #pragma unroll
            for (int k = 0; k < 4; k++) acc[i][j][k] = 0.f;

    int nk = K >> 4;

    #define LOAD_STAGE(kt) {                                                   \
        int st_ = (kt) & 3;                                                    \
        float* as_ = Abuf + st_ * (128 * LDT);                                 \
        float* ws_ = Wbuf + st_ * (128 * LDT);                                 \
        cp16(as_ + r0 * LDT + s0, A + (size_t)(bm + r0) * lda + (kt) * 16 + s0); \
        cp16(as_ + r1 * LDT + s1, A + (size_t)(bm + r1) * lda + (kt) * 16 + s1); \
        cp16(ws_ + r0 * LDT + s0, W + (size_t)(bn + r0) * K + (kt) * 16 + s0); \
        cp16(ws_ + r1 * LDT + s1, W + (size_t)(bn + r1) * K + (kt) * 16 + s1); \
    }

    #pragma unroll
    for (int s = 0; s < 3; s++) {
        if (s < nk) LOAD_STAGE(s);
        cp_commit();
    }

    for (int kt = 0; kt < nk; kt++) {
        cp_wait<2>();
        __syncthreads();
        if (kt + 3 < nk) LOAD_STAGE(kt + 3);
        cp_commit();

        const float* as = Abuf + (kt & 3) * (128 * LDT);
        const float* ws = Wbuf + (kt & 3) * (128 * LDT);
        #pragma unroll
        for (int ks = 0; ks < 2; ks++) {
            int kk = ks * 8;
            uint32_t af[2][4], bf[8][2];
            #pragma unroll
            for (int mi = 0; mi < 2; mi++) {
                int mr = wm + mi * 16 + gr;
                af[mi][0] = __float_as_uint(as[(size_t)mr * LDT + kk + ct]);
                af[mi][1] = __float_as_uint(as[(size_t)(mr + 8) * LDT + kk + ct]);
                af[mi][2] = __float_as_uint(as[(size_t)mr * LDT + kk + ct + 4]);
                af[mi][3] = __float_as_uint(as[(size_t)(mr + 8) * LDT + kk + ct + 4]);
            }
            #pragma unroll
            for (int ni = 0; ni < 8; ni++) {
                int nc = wn + ni * 8 + gr;
                bf[ni][0] = __float_as_uint(ws[(size_t)nc * LDT + kk + ct]);
                bf[ni][1] = __float_as_uint(ws[(size_t)nc * LDT + kk + ct + 4]);
            }
            #pragma unroll
            for (int mi = 0; mi < 2; mi++)
                #pragma unroll
                for (int ni = 0; ni < 8; ni++)
                    mma_tf32(acc[mi][ni], af[mi], bf[ni]);
        }
    }
    #undef LOAD_STAGE

    #pragma unroll
    for (int mi = 0; mi < 2; mi++) {
        #pragma unroll
        for (int half = 0; half < 2; half++) {
            int row = bm + wm + mi * 16 + gr + half * 8;
            #pragma unroll
            for (int ni = 0; ni < 8; ni++) {
                int col = bn + wn + ni * 8 + ct * 2;
                float v0 = acc[mi][ni][half * 2 + 0];
                float v1 = acc[mi][ni][half * 2 + 1];
                if (bias) { v0 += bias[col]; v1 += bias[col + 1]; }
                if (EPI == 1) {
                    v0 = (v0 > 20.f) ? v0 : __logf(1.f + fexp(v0));
                    v1 = (v1 > 20.f) ? v1 : __logf(1.f + fexp(v1));
                }
                if (EPI == 2) {
                    const float* rr = res + (size_t)row * ldc;
                    v0 += rr[col]; v1 += rr[col + 1];
                }
                *(float2*)(C + (size_t)row * ldc + col) = make_float2(v0, v1);
            }
        }
    }
}

// ---------------- GEMM2 split-K (M=2048, N=96, K=2048) ----------------
__global__ void __launch_bounds__(256)
gemm2_splitk(const float* __restrict__ A,
             const float* __restrict__ W,
             float* __restrict__ part)
{
    const int KC = DI / NSPLIT;   // 128
    __shared__ float As[16][68];
    __shared__ float Ws[16][100];
    int bm = blockIdx.x * 64;
    int ks = blockIdx.y;
    int k0 = ks * KC;
    int t = threadIdx.x;
    int tr = t >> 4, tc = t & 15;

    float acc[4][6];
    #pragma unroll
    for (int i = 0; i < 4; i++)
        #pragma unroll
        for (int j = 0; j < 6; j++) acc[i][j] = 0.f;

    for (int kk = 0; kk < KC; kk += 16) {
        int arow = t >> 2, aseg = (t & 3) * 4;
        float4 av = *(const float4*)(A + (size_t)(bm + arow) * DI + k0 + kk + aseg);
        As[aseg+0][arow] = av.x; As[aseg+1][arow] = av.y;
        As[aseg+2][arow] = av.z; As[aseg+3][arow] = av.w;
        #pragma unroll
        for (int p = 0; p < 2; p++) {
            int idx = t + p * 256;
            if (idx < 384) {
                int wrow = idx >> 2, wseg = (idx & 3) * 4;
                float4 wv = *(const float4*)(W + (size_t)wrow * DI + k0 + kk + wseg);
                Ws[wseg+0][wrow] = wv.x; Ws[wseg+1][wrow] = wv.y;
                Ws[wseg+2][wrow] = wv.z; Ws[wseg+3][wrow] = wv.w;
            }
        }
        __syncthreads();
        #pragma unroll
        for (int k = 0; k < 16; k++) {
            float ar[4], wr[6];
            #pragma unroll
            for (int i = 0; i < 4; i++) ar[i] = As[k][tr * 4 + i];
            #pragma unroll
            for (int j = 0; j < 6; j++) wr[j] = Ws[k][tc * 6 + j];
            #pragma unroll
            for (int i = 0; i < 4; i++)
                #pragma unroll
                for (int j = 0; j < 6; j++)
                    acc[i][j] = fmaf(ar[i], wr[j], acc[i][j]);
        }
        __syncthreads();
    }
    #pragma unroll
    for (int i = 0; i < 4; i++)
        #pragma unroll
        for (int j = 0; j < 6; j++)
            part[((size_t)ks * BL + bm + tr * 4 + i) * 96 + tc * 6 + j] = acc[i][j];
}

// reduce + tf32-round the dt_lo columns (0..63) for GEMM5
__global__ void reduce_split(const float* __restrict__ p, float* __restrict__ o)
{
    int i = blockIdx.x * 256 + threadIdx.x;
    if (i < BL * 96) {
        float s = 0.f;
        #pragma unroll
        for (int k = 0; k < NSPLIT; k++) s += p[(size_t)k * BL * 96 + i];
        int col = i % 96;
        o[i] = (col < 64) ? rtf(s) : s;
    }
}

// ---------------- depthwise causal conv + SiLU ----------------
__global__ void conv_silu(const float* __restrict__ xz, const float* __restrict__ cw,
                          const float* __restrict__ cb, float* __restrict__ xc)
{
    int idx = blockIdx.x * blockDim.x + threadIdx.x;
    if (idx >= BL * DI) return;
    int d  = idx & (DI - 1);
    int bl = idx >> 11;
    int l  = bl & (L_SZ - 1);
    float acc = cb[d];
    #pragma unroll
    for (int k = 0; k < DCONV; k++) {
        int li = l - (DCONV - 1) + k;
        if (li >= 0)
            acc = fmaf(xz[(size_t)(bl - (DCONV - 1 - k)) * (2 * DI) + d],
                       cw[d * DCONV + k], acc);
    }
    float sg = 1.f / (1.f + fexp(-acc));
    xc[idx] = acc * sg;
}

// ---------------- chunked selective scan ----------------
__global__ void __launch_bounds__(256)
scan_pass1(const float* __restrict__ dt, const float* __restrict__ xc,
           const float* __restrict__ xdbl, const float* __restrict__ A_log,
           float* __restrict__ hq, float* __restrict__ hP)
{
    int t = threadIdx.x;
    int s = t & 15;
    int g = t >> 4;
    int d = blockIdx.x * 16 + g;
    int c = blockIdx.y;
    int b = blockIdx.z;
    float a = -fexp(A_log[d * DS + s]);
    float h = 0.f, P = 1.f;
    int base = b * L_SZ + c * LC;
    #pragma unroll 4
    for (int l = 0; l < LC; l++) {
        int bl = base + l;
        float dtv = dt[(size_t)bl * DI + d];
        float xcv = xc[(size_t)bl * DI + d];
        float Bv  = xdbl[(size_t)bl * 96 + 64 + s];
        float dA  = fexp(dtv * a);
        h = fmaf(dA, h, dtv * xcv * Bv);
        P *= dA;
    }
    size_t idx = ((size_t)(b * NCH + c) * DI + d) * DS + s;
    hq[idx] = h;
    hP[idx] = P;
}

__global__ void scan_fix(const float* __restrict__ hq, const float* __restrict__ hP,
                         float* __restrict__ h0)
{
    int i = blockIdx.x * 256 + threadIdx.x;       // over B*DI*DS = 65536
    if (i >= B_SZ * DI * DS) return;
    int s = i & 15;
    int d = (i >> 4) & (DI - 1);
    int b = i >> 15;
    float h = 0.f;
    #pragma unroll
    for (int c = 0; c < NCH; c++) {
        size_t idx = ((size_t)(b * NCH + c) * DI + d) * DS + s;
        h0[idx] = h;
        h = fmaf(hP[idx], h, hq[idx]);
    }
}

__global__ void __launch_bounds__(256)
scan_pass2(const float* __restrict__ dt, const float* __restrict__ xc,
           const float* __restrict__ xdbl, const float* __restrict__ A_log,
           const float* __restrict__ Dp, const float* __restrict__ xz,
           const float* __restrict__ h0, float* __restrict__ y)
{
    int t = threadIdx.x;
    int s = t & 15;
    int g = t >> 4;
    int d = blockIdx.x * 16 + g;
    int c = blockIdx.y;
    int b = blockIdx.z;
    float a = -fexp(A_log[d * DS + s]);
    float dscale = Dp[d];
    float h = h0[((size_t)(b * NCH + c) * DI + d) * DS + s];
    int base = b * L_SZ + c * LC;
    #pragma unroll 2
    for (int l = 0; l < LC; l++) {
        int bl = base + l;
        float dtv = dt[(size_t)bl * DI + d];
        float xcv = xc[(size_t)bl * DI + d];
        float Bv  = xdbl[(size_t)bl * 96 + 64 + s];
        float Cv  = xdbl[(size_t)bl * 96 + 80 + s];
        float dA  = fexp(dtv * a);
        h = fmaf(dA, h, dtv * xcv * Bv);
        float yp = h * Cv;
        yp += __shfl_xor_sync(0xffffffffu, yp, 8);
        yp += __shfl_xor_sync(0xffffffffu, yp, 4);
        yp += __shfl_xor_sync(0xffffffffu, yp, 2);
        yp += __shfl_xor_sync(0xffffffffu, yp, 1);
        if (s == 0) {
            float zv = xz[(size_t)bl * (2 * DI) + DI + d];
            float sz = zv / (1.f + fexp(-zv));
            y[(size_t)bl * DI + d] = rtf((yp + dscale * xcv) * sz);
        }
    }
}

// ---------------- host launcher ----------------
extern "C" void kernel_launch(void* const* d_in, const int* in_sizes, int n_in,
                              void* d_out, int out_size)
{
    const float* x      = (const float*)d_in[0];
    const float* ln_g   = (const float*)d_in[1];
    const float* ln_b   = (const float*)d_in[2];
    const float* W_in   = (const float*)d_in[3];
    const float* b_in   = (const float*)d_in[4];
    const float* conv_w = (const float*)d_in[5];
    const float* conv_b = (const float*)d_in[6];
    const float* W_x    = (const float*)d_in[7];
    const float* W_dt   = (const float*)d_in[8];
    const float* b_dt   = (const float*)d_in[9];
    const float* A_log  = (const float*)d_in[10];
    const float* Dv     = (const float*)d_in[11];
    const float* W_out  = (const float*)d_in[12];
    const float* b_out  = (const float*)d_in[13];
    float* out = (float*)d_out;

    float *xn, *xz, *xc, *xdbl, *x2p, *dtb, *yb, *hq, *hP, *h0;
    float *rWin, *rWdt, *rWout;
    cudaGetSymbolAddress((void**)&xn,   g_xn);
    cudaGetSymbolAddress((void**)&xz,   g_xz);
    cudaGetSymbolAddress((void**)&xc,   g_xc);
    cudaGetSymbolAddress((void**)&xdbl, g_xdbl);
    cudaGetSymbolAddress((void**)&x2p,  g_x2p);
    cudaGetSymbolAddress((void**)&dtb,  g_dt);
    cudaGetSymbolAddress((void**)&yb,   g_y);
    cudaGetSymbolAddress((void**)&hq,   g_hq);
    cudaGetSymbolAddress((void**)&hP,   g_hP);
    cudaGetSymbolAddress((void**)&h0,   g_h0);
    cudaGetSymbolAddress((void**)&rWin, g_rWin);
    cudaGetSymbolAddress((void**)&rWdt, g_rWdt);
    cudaGetSymbolAddress((void**)&rWout,g_rWout);

    static bool attr_done = false;
    if (!attr_done) {
        cudaFuncSetAttribute(gemm_tf32<0>, cudaFuncAttributeMaxDynamicSharedMemorySize, GSM);
        cudaFuncSetAttribute(gemm_tf32<1>, cudaFuncAttributeMaxDynamicSharedMemorySize, GSM);
        cudaFuncSetAttribute(gemm_tf32<2>, cudaFuncAttributeMaxDynamicSharedMemorySize, GSM);
        attr_done = true;
    }

    // 0. pre-round weights to tf32 (scratch copies)
    cvt_tf32<<<(2 * DI * DM / 4 + 255) / 256, 256>>>(W_in,  rWin,  2 * DI * DM / 4);
    cvt_tf32<<<(DI * DTR    / 4 + 255) / 256, 256>>>(W_dt,  rWdt,  DI * DTR / 4);
    cvt_tf32<<<(DM * DI     / 4 + 255) / 256, 256>>>(W_out, rWout, DM * DI / 4);

    // 1. LayerNorm (tf32-rounded output)
    ln_kernel<<<BL, 256>>>(x, ln_g, ln_b, xn);

    // 2. in-projection (tf32 TC, cp.async pipelined)
    gemm_tf32<0><<<dim3(4096 / 128, BL / 128), 256, GSM>>>(
        xn, DM, rWin, b_in, nullptr, xz, 2 * DI, DM);

    // 3. depthwise conv + SiLU
    conv_silu<<<(BL * DI) / 256, 256>>>(xz, conv_w, conv_b, xc);

    // 4. x_dbl = xc @ W_x^T (split-K, fp32)
    gemm2_splitk<<<dim3(BL / 64, NSPLIT), 256>>>(xc, W_x, x2p);
    reduce_split<<<(BL * 96 + 255) / 256, 256>>>(x2p, xdbl);

    // 5. dt = softplus(dt_lo @ W_dt^T + b_dt)
    gemm_tf32<1><<<dim3(DI / 128, BL / 128), 256, GSM>>>(
        xdbl, 96, rWdt, b_dt, nullptr, dtb, DI, DTR);

    // 6. chunked selective scan
    scan_pass1<<<dim3(DI / 16, NCH, B_SZ), 256>>>(dtb, xc, xdbl, A_log, hq, hP);
    scan_fix<<<(B_SZ * DI * DS) / 256, 256>>>(hq, hP, h0);
    scan_pass2<<<dim3(DI / 16, NCH, B_SZ), 256>>>(dtb, xc, xdbl, A_log, Dv, xz, h0, yb);

    // 7. out-projection + residual
    gemm_tf32<2><<<dim3(DM / 128, BL / 128), 256, GSM>>>(
        yb, DI, rWout, b_out, x, out, DM, DI);
}

// round 14
// speedup vs baseline: 3.4698x; 1.0871x over previous
#include <cuda_runtime.h>
#include <math.h>
#include <stdint.h>

#define B_SZ   2
#define L_SZ   1024
#define DM     1024
#define DI     2048
#define DS     16
#define DTR    64
#define DCONV  4
#define BL     (B_SZ * L_SZ)   // 2048 rows
#define NSPLIT 16              // k-slices for fused conv+GEMM2
#define KC     (DI / NSPLIT)   // 128 channels per slice
#define NCH    8               // scan chunks per sequence
#define LC     (L_SZ / NCH)    // 128 steps per chunk

#define LDT    20                              // gemm smem row stride (words)
#define GSM    (4 * 2 * 128 * LDT * 4)         // gemm dynamic smem: 81920 B

// ---------------- scratch (static device globals; no allocation) ----------------
__device__ float g_xn  [BL * DM];
__device__ float g_xz  [BL * 2 * DI];
__device__ float g_xc  [BL * DI];
__device__ float g_xdbl[BL * 96];
__device__ float g_x2p [NSPLIT * BL * 96];
__device__ float g_dt  [BL * DI];
__device__ float g_y   [BL * DI];
__device__ float g_hq  [B_SZ * NCH * DI * DS];
__device__ float g_hP  [B_SZ * NCH * DI * DS];
__device__ float g_rWin [2 * DI * DM];   // tf32-rounded weights
__device__ float g_rWdt [DI * DTR];
__device__ float g_rWout[DM * DI];

// ---------------- helpers ----------------
__device__ __forceinline__ uint32_t f2tf32(float v)
{
    uint32_t r;
    asm("cvt.rna.tf32.f32 %0, %1;" : "=r"(r) : "f"(v));
    return r;
}
__device__ __forceinline__ float rtf(float v) { return __uint_as_float(f2tf32(v)); }

__device__ __forceinline__ void mma_tf32(float* d, const uint32_t* a, const uint32_t* b)
{
    asm volatile(
        "mma.sync.aligned.m16n8k8.row.col.f32.tf32.tf32.f32 "
        "{%0,%1,%2,%3}, {%4,%5,%6,%7}, {%8,%9}, {%0,%1,%2,%3};\n"
        : "+f"(d[0]), "+f"(d[1]), "+f"(d[2]), "+f"(d[3])
        : "r"(a[0]), "r"(a[1]), "r"(a[2]), "r"(a[3]), "r"(b[0]), "r"(b[1]));
}

__device__ __forceinline__ void cp16(float* smem, const float* g)
{
    uint32_t sa = (uint32_t)__cvta_generic_to_shared(smem);
    asm volatile("cp.async.cg.shared.global [%0], [%1], 16;\n" :: "r"(sa), "l"(g));
}
__device__ __forceinline__ void cp_commit() { asm volatile("cp.async.commit_group;\n"); }
template<int N>
__device__ __forceinline__ void cp_wait() { asm volatile("cp.async.wait_group %0;\n" :: "n"(N)); }

// ---------------- tf32 weight pre-rounding (all three weights, one kernel) ----------------
#define N4_WIN  (2 * DI * DM / 4)
#define N4_WDT  (DI * DTR / 4)
#define N4_WOUT (DM * DI / 4)
__global__ void cvt_all(const float* __restrict__ Win, const float* __restrict__ Wdt,
                        const float* __restrict__ Wout, float* __restrict__ rWin,
                        float* __restrict__ rWdt, float* __restrict__ rWout)
{
    int i = blockIdx.x * 256 + threadIdx.x;
    const float4* src; float4* dst; int j;
    if (i < N4_WIN) { src = (const float4*)Win; dst = (float4*)rWin; j = i; }
    else if (i < N4_WIN + N4_WDT) { src = (const float4*)Wdt; dst = (float4*)rWdt; j = i - N4_WIN; }
    else if (i < N4_WIN + N4_WDT + N4_WOUT) { src = (const float4*)Wout; dst = (float4*)rWout; j = i - N4_WIN - N4_WDT; }
    else return;
    float4 v = src[j];
    v.x = rtf(v.x); v.y = rtf(v.y); v.z = rtf(v.z); v.w = rtf(v.w);
    dst[j] = v;
}

// ---------------- single-pass LayerNorm (tf32-rounded output) ----------------
__global__ void ln_kernel(const float* __restrict__ x, const float* __restrict__ g,
                          const float* __restrict__ b, float* __restrict__ out)
{
    int row = blockIdx.x;
    int t = threadIdx.x;                      // 256 threads, one float4 each
    float4 v = ((const float4*)(x + (size_t)row * DM))[t];
    float s  = v.x + v.y + v.z + v.w;
    float s2 = v.x*v.x + v.y*v.y + v.z*v.z + v.w*v.w;
    __shared__ float sh[18];
    #pragma unroll
    for (int o = 16; o > 0; o >>= 1) {
        s  += __shfl_xor_sync(0xffffffffu, s,  o);
        s2 += __shfl_xor_sync(0xffffffffu, s2, o);
    }
    int wid = t >> 5, lid = t & 31;
    if (lid == 0) { sh[wid] = s; sh[8 + wid] = s2; }
    __syncthreads();
    if (t == 0) {
        float a = 0.f, c = 0.f;
        #pragma unroll
        for (int w = 0; w < 8; w++) { a += sh[w]; c += sh[8 + w]; }
        float mu = a / DM;
        float var = c / DM - mu * mu;
        sh[16] = mu; sh[17] = rsqrtf(var + 1e-5f);
    }
    __syncthreads();
    float mu = sh[16], rs = sh[17];
    float4 gg = ((const float4*)g)[t];
    float4 bb = ((const float4*)b)[t];
    float4 o4;
    o4.x = rtf((v.x - mu) * rs * gg.x + bb.x);
    o4.y = rtf((v.y - mu) * rs * gg.y + bb.y);
    o4.z = rtf((v.z - mu) * rs * gg.z + bb.z);
    o4.w = rtf((v.w - mu) * rs * gg.w + bb.w);
    ((float4*)(out + (size_t)row * DM))[t] = o4;
}

// ---------------- tf32 TC GEMM, 4-stage cp.async pipeline ----------------
template<int EPI>
__global__ void __launch_bounds__(256)
gemm_tf32(const float* __restrict__ A, int lda,
          const float* __restrict__ W,
          const float* __restrict__ bias,
          const float* __restrict__ res,
          float* __restrict__ C, int ldc, int K)
{
    extern __shared__ float smem[];
    float* Abuf = smem;                       // [4][128][LDT]
    float* Wbuf = smem + 4 * 128 * LDT;

    int bm = blockIdx.y * 128, bn = blockIdx.x * 128;
    int t = threadIdx.x;
    int lane = t & 31, wid = t >> 5;
    int gr = lane >> 2, ct = lane & 3;
    int wm = (wid & 3) * 32, wn = (wid >> 2) * 64;

    int c0 = t * 2, c1 = t * 2 + 1;
    int r0 = c0 >> 2, s0 = (c0 & 3) * 4;
    int r1 = c1 >> 2, s1 = (c1 & 3) * 4;

    float acc[2][8][4];
    #pragma unroll
    for (int i = 0; i < 2; i++)
        #pragma unroll
        for (int j = 0; j < 8; j++)
            #pragma unroll
            for (int k = 0; k < 4; k++) acc[i][j][k] = 0.f;

    int nk = K >> 4;

    #define LOAD_STAGE(kt) {                                                   \
        int st_ = (kt) & 3;                                                    \
        float* as_ = Abuf + st_ * (128 * LDT);                                 \
        float* ws_ = Wbuf + st_ * (128 * LDT);                                 \
        cp16(as_ + r0 * LDT + s0, A + (size_t)(bm + r0) * lda + (kt) * 16 + s0); \
        cp16(as_ + r1 * LDT + s1, A + (size_t)(bm + r1) * lda + (kt) * 16 + s1); \
        cp16(ws_ + r0 * LDT + s0, W + (size_t)(bn + r0) * K + (kt) * 16 + s0); \
        cp16(ws_ + r1 * LDT + s1, W + (size_t)(bn + r1) * K + (kt) * 16 + s1); \
    }

    #pragma unroll
    for (int s = 0; s < 3; s++) {
        if (s < nk) LOAD_STAGE(s);
        cp_commit();
    }

    for (int kt = 0; kt < nk; kt++) {
        cp_wait<2>();
        __syncthreads();
        if (kt + 3 < nk) LOAD_STAGE(kt + 3);
        cp_commit();

        const float* as = Abuf + (kt & 3) * (128 * LDT);
        const float* ws = Wbuf + (kt & 3) * (128 * LDT);
        #pragma unroll
        for (int ks = 0; ks < 2; ks++) {
            int kk = ks * 8;
            uint32_t af[2][4], bf[8][2];
            #pragma unroll
            for (int mi = 0; mi < 2; mi++) {
                int mr = wm + mi * 16 + gr;
                af[mi][0] = __float_as_uint(as[(size_t)mr * LDT + kk + ct]);
                af[mi][1] = __float_as_uint(as[(size_t)(mr + 8) * LDT + kk + ct]);
                af[mi][2] = __float_as_uint(as[(size_t)mr * LDT + kk + ct + 4]);
                af[mi][3] = __float_as_uint(as[(size_t)(mr + 8) * LDT + kk + ct + 4]);
            }
            #pragma unroll
            for (int ni = 0; ni < 8; ni++) {
                int nc = wn + ni * 8 + gr;
                bf[ni][0] = __float_as_uint(ws[(size_t)nc * LDT + kk + ct]);
                bf[ni][1] = __float_as_uint(ws[(size_t)nc * LDT + kk + ct + 4]);
            }
            #pragma unroll
            for (int mi = 0; mi < 2; mi++)
                #pragma unroll
                for (int ni = 0; ni < 8; ni++)
                    mma_tf32(acc[mi][ni], af[mi], bf[ni]);
        }
    }
    #undef LOAD_STAGE

    #pragma unroll
    for (int mi = 0; mi < 2; mi++) {
        #pragma unroll
        for (int half = 0; half < 2; half++) {
            int row = bm + wm + mi * 16 + gr + half * 8;
            #pragma unroll
            for (int ni = 0; ni < 8; ni++) {
                int col = bn + wn + ni * 8 + ct * 2;
                float v0 = acc[mi][ni][half * 2 + 0];
                float v1 = acc[mi][ni][half * 2 + 1];
                if (bias) { v0 += bias[col]; v1 += bias[col + 1]; }
                if (EPI == 1) {
                    v0 = (v0 > 20.f) ? v0 : __logf(1.f + __expf(v0));
                    v1 = (v1 > 20.f) ? v1 : __logf(1.f + __expf(v1));
                }
                if (EPI == 2) {
                    const float* rr = res + (size_t)row * ldc;
                    v0 += rr[col]; v1 += rr[col + 1];
                }
                *(float2*)(C + (size_t)row * ldc + col) = make_float2(v0, v1);
            }
        }
    }
}

// ---------------- fused depthwise conv + SiLU + GEMM2 split-K ----------------
// Block (bm, ks): computes xc[bm:bm+64, ks*128:(ks+1)*128] from xz via causal conv,
// writes it to gmem, and accumulates the GEMM2 partial for that k-slice.
__global__ void __launch_bounds__(256)
conv_gemm2(const float* __restrict__ xz, const float* __restrict__ cw,
           const float* __restrict__ cb, const float* __restrict__ W,
           float* __restrict__ xc, float* __restrict__ part)
{
    __shared__ float XC[KC][68];     // [channel][row]
    __shared__ float Ws[16][100];
    int bm = blockIdx.x * 64;
    int ks = blockIdx.y;
    int k0 = ks * KC;
    int t = threadIdx.x;

    // --- conv + SiLU: thread owns channel ch, 32 rows (sliding window) ---
    {
        int ch = t & 127;
        int rg = t >> 7;               // 0 or 1
        int d  = k0 + ch;
        float w0 = cw[d * 4 + 0], w1 = cw[d * 4 + 1];
        float w2 = cw[d * 4 + 2], w3 = cw[d * 4 + 3];
        float bconv = cb[d];
        int rbeg = rg * 32;
        int bl0 = bm + rbeg;
        int l0  = bl0 & (L_SZ - 1);
        float xm3 = (l0 >= 3) ? xz[(size_t)(bl0 - 3) * (2 * DI) + d] : 0.f;
        float xm2 = (l0 >= 2) ? xz[(size_t)(bl0 - 2) * (2 * DI) + d] : 0.f;
        float xm1 = (l0 >= 1) ? xz[(size_t)(bl0 - 1) * (2 * DI) + d] : 0.f;
        #pragma unroll 4
        for (int r = rbeg; r < rbeg + 32; r++) {
            int bl = bm + r;
            float x0 = xz[(size_t)bl * (2 * DI) + d];
            float acc = bconv;
            acc = fmaf(xm3, w0, acc);
            acc = fmaf(xm2, w1, acc);
            acc = fmaf(xm1, w2, acc);
            acc = fmaf(x0,  w3, acc);
            float v = acc / (1.f + __expf(-acc));
            XC[ch][r - (bm & 0)] = v;          // row index r (0..63)
            xc[(size_t)bl * DI + d] = v;
            xm3 = xm2; xm2 = xm1; xm1 = x0;
        }
    }
    __syncthreads();

    // --- GEMM partial: part[ks] += XC^T tile x W slice ---
    int tr = t >> 4, tc = t & 15;
    float acc[4][6];
    #pragma unroll
    for (int i = 0; i < 4; i++)
        #pragma unroll
        for (int j = 0; j < 6; j++) acc[i][j] = 0.f;

    for (int kk = 0; kk < KC; kk += 16) {
        #pragma unroll
        for (int p = 0; p < 2; p++) {
            int idx = t + p * 256;
            if (idx < 384) {
                int wrow = idx >> 2, wseg = (idx & 3) * 4;
                float4 wv = *(const float4*)(W + (size_t)wrow * DI + k0 + kk + wseg);
                Ws[wseg+0][wrow] = wv.x; Ws[wseg+1][wrow] = wv.y;
                Ws[wseg+2][wrow] = wv.z; Ws[wseg+3][wrow] = wv.w;
            }
        }
        __syncthreads();
        #pragma unroll
        for (int k = 0; k < 16; k++) {
            float ar[4], wr[6];
            #pragma unroll
            for (int i = 0; i < 4; i++) ar[i] = XC[kk + k][tr * 4 + i];
            #pragma unroll
            for (int j = 0; j < 6; j++) wr[j] = Ws[k][tc * 6 + j];
            #pragma unroll
            for (int i = 0; i < 4; i++)
                #pragma unroll
                for (int j = 0; j < 6; j++)
                    acc[i][j] = fmaf(ar[i], wr[j], acc[i][j]);
        }
        __syncthreads();
    }
    #pragma unroll
    for (int i = 0; i < 4; i++)
        #pragma unroll
        for (int j = 0; j < 6; j++)
            part[((size_t)ks * BL + bm + tr * 4 + i) * 96 + tc * 6 + j] = acc[i][j];
}

// reduce + tf32-round the dt_lo columns (0..63) for GEMM5
__global__ void reduce_split(const float* __restrict__ p, float* __restrict__ o)
{
    int i = blockIdx.x * 256 + threadIdx.x;
    if (i < BL * 96) {
        float s = 0.f;
        #pragma unroll
        for (int k = 0; k < NSPLIT; k++) s += p[(size_t)k * BL * 96 + i];
        int col = i % 96;
        o[i] = (col < 64) ? rtf(s) : s;
    }
}

// ---------------- chunked selective scan (MUFU exp) ----------------
__global__ void __launch_bounds__(256)
scan_pass1(const float* __restrict__ dt, const float* __restrict__ xc,
           const float* __restrict__ xdbl, const float* __restrict__ A_log,
           float* __restrict__ hq, float* __restrict__ hP)
{
    int t = threadIdx.x;
    int s = t & 15;
    int g = t >> 4;
    int d = blockIdx.x * 16 + g;
    int c = blockIdx.y;
    int b = blockIdx.z;
    float a = -__expf(A_log[d * DS + s]);
    float h = 0.f, P = 1.f;
    int base = b * L_SZ + c * LC;
    #pragma unroll 8
    for (int l = 0; l < LC; l++) {
        int bl = base + l;
        float dtv = dt[(size_t)bl * DI + d];
        float xcv = xc[(size_t)bl * DI + d];
        float Bv  = xdbl[(size_t)bl * 96 + 64 + s];
        float dA  = __expf(dtv * a);
        h = fmaf(dA, h, dtv * xcv * Bv);
        P *= dA;
    }
    size_t idx = ((size_t)(b * NCH + c) * DI + d) * DS + s;
    hq[idx] = h;
    hP[idx] = P;
}

// pass 2: computes its own h0 from chunk prefixes (scan_fix folded in)
__global__ void __launch_bounds__(256)
scan_pass2(const float* __restrict__ dt, const float* __restrict__ xc,
           const float* __restrict__ xdbl, const float* __restrict__ A_log,
           const float* __restrict__ Dp, const float* __restrict__ xz,
           const float* __restrict__ hq, const float* __restrict__ hP,
           float* __restrict__ y)
{
    int t = threadIdx.x;
    int s = t & 15;
    int g = t >> 4;
    int d = blockIdx.x * 16 + g;
    int c = blockIdx.y;
    int b = blockIdx.z;
    float a = -__expf(A_log[d * DS + s]);
    float dscale = Dp[d];
    // inline fixup: h0 = scan of (P,q) over chunks 0..c-1
    float h = 0.f;
    for (int cc = 0; cc < c; cc++) {
        size_t idx = ((size_t)(b * NCH + cc) * DI + d) * DS + s;
        h = fmaf(hP[idx], h, hq[idx]);
    }
    int base = b * L_SZ + c * LC;
    #pragma unroll 4
    for (int l = 0; l < LC; l++) {
        int bl = base + l;
        float dtv = dt[(size_t)bl * DI + d];
        float xcv = xc[(size_t)bl * DI + d];
        float Bv  = xdbl[(size_t)bl * 96 + 64 + s];
        float Cv  = xdbl[(size_t)bl * 96 + 80 + s];
        float dA  = __expf(dtv * a);
        h = fmaf(dA, h, dtv * xcv * Bv);
        float yp = h * Cv;
        yp += __shfl_xor_sync(0xffffffffu, yp, 8);
        yp += __shfl_xor_sync(0xffffffffu, yp, 4);
        yp += __shfl_xor_sync(0xffffffffu, yp, 2);
        yp += __shfl_xor_sync(0xffffffffu, yp, 1);
        if (s == 0) {
            float zv = xz[(size_t)bl * (2 * DI) + DI + d];
            float sz = zv / (1.f + __expf(-zv));
            y[(size_t)bl * DI + d] = rtf((yp + dscale * xcv) * sz);
        }
    }
}

// ---------------- host launcher ----------------
extern "C" void kernel_launch(void* const* d_in, const int* in_sizes, int n_in,
                              void* d_out, int out_size)
{
    const float* x      = (const float*)d_in[0];
    const float* ln_g   = (const float*)d_in[1];
    const float* ln_b   = (const float*)d_in[2];
    const float* W_in   = (const float*)d_in[3];
    const float* b_in   = (const float*)d_in[4];
    const float* conv_w = (const float*)d_in[5];
    const float* conv_b = (const float*)d_in[6];
    const float* W_x    = (const float*)d_in[7];
    const float* W_dt   = (const float*)d_in[8];
    const float* b_dt   = (const float*)d_in[9];
    const float* A_log  = (const float*)d_in[10];
    const float* Dv     = (const float*)d_in[11];
    const float* W_out  = (const float*)d_in[12];
    const float* b_out  = (const float*)d_in[13];
    float* out = (float*)d_out;

    float *xn, *xz, *xc, *xdbl, *x2p, *dtb, *yb, *hq, *hP;
    float *rWin, *rWdt, *rWout;
    cudaGetSymbolAddress((void**)&xn,   g_xn);
    cudaGetSymbolAddress((void**)&xz,   g_xz);
    cudaGetSymbolAddress((void**)&xc,   g_xc);
    cudaGetSymbolAddress((void**)&xdbl, g_xdbl);
    cudaGetSymbolAddress((void**)&x2p,  g_x2p);
    cudaGetSymbolAddress((void**)&dtb,  g_dt);
    cudaGetSymbolAddress((void**)&yb,   g_y);
    cudaGetSymbolAddress((void**)&hq,   g_hq);
    cudaGetSymbolAddress((void**)&hP,   g_hP);
    cudaGetSymbolAddress((void**)&rWin, g_rWin);
    cudaGetSymbolAddress((void**)&rWdt, g_rWdt);
    cudaGetSymbolAddress((void**)&rWout,g_rWout);

    static bool attr_done = false;
    if (!attr_done) {
        cudaFuncSetAttribute(gemm_tf32<0>, cudaFuncAttributeMaxDynamicSharedMemorySize, GSM);
        cudaFuncSetAttribute(gemm_tf32<1>, cudaFuncAttributeMaxDynamicSharedMemorySize, GSM);
        cudaFuncSetAttribute(gemm_tf32<2>, cudaFuncAttributeMaxDynamicSharedMemorySize, GSM);
        attr_done = true;
    }

    // 0. pre-round all weights to tf32 (one kernel)
    cvt_all<<<(N4_WIN + N4_WDT + N4_WOUT + 255) / 256, 256>>>(
        W_in, W_dt, W_out, rWin, rWdt, rWout);

    // 1. single-pass LayerNorm (tf32-rounded output)
    ln_kernel<<<BL, 256>>>(x, ln_g, ln_b, xn);

    // 2. in-projection (tf32 TC, cp.async pipelined)
    gemm_tf32<0><<<dim3(4096 / 128, BL / 128), 256, GSM>>>(
        xn, DM, rWin, b_in, nullptr, xz, 2 * DI, DM);

    // 3+4. fused conv+SiLU+GEMM2 split-K, then reduce
    conv_gemm2<<<dim3(BL / 64, NSPLIT), 256>>>(xz, conv_w, conv_b, W_x, xc, x2p);
    reduce_split<<<(BL * 96 + 255) / 256, 256>>>(x2p, xdbl);

    // 5. dt = softplus(dt_lo @ W_dt^T + b_dt)
    gemm_tf32<1><<<dim3(DI / 128, BL / 128), 256, GSM>>>(
        xdbl, 96, rWdt, b_dt, nullptr, dtb, DI, DTR);

    // 6. chunked selective scan (fixup folded into pass2)
    scan_pass1<<<dim3(DI / 16, NCH, B_SZ), 256>>>(dtb, xc, xdbl, A_log, hq, hP);
    scan_pass2<<<dim3(DI / 16, NCH, B_SZ), 256>>>(dtb, xc, xdbl, A_log, Dv, xz, hq, hP, yb);

    // 7. out-projection + residual
    gemm_tf32<2><<<dim3(DM / 128, BL / 128), 256, GSM>>>(
        yb, DI, rWout, b_out, x, out, DM, DI);
}

// round 15
// speedup vs baseline: 4.0714x; 1.1734x over previous
#include <cuda_runtime.h>
#include <math.h>
#include <stdint.h>

#define B_SZ   2
#define L_SZ   1024
#define DM     1024
#define DI     2048
#define DS     16
#define DTR    64
#define DCONV  4
#define BL     (B_SZ * L_SZ)   // 2048 rows
#define NSPLIT 16              // k-slices for fused conv+GEMM2
#define KC     (DI / NSPLIT)   // 128 channels per slice
#define NCH    8               // scan chunks per sequence
#define LC     (L_SZ / NCH)    // 128 steps per chunk

#define LDT    20                              // gemm smem row stride (words)
#define GSM    (4 * 2 * 128 * LDT * 4)         // gemm dynamic smem: 81920 B

// ---------------- scratch (static device globals; no allocation) ----------------
__device__ float g_xn  [BL * DM];
__device__ float g_xz  [BL * 2 * DI];
__device__ float g_xc  [BL * DI];
__device__ float g_xdbl[BL * 96];
__device__ float g_x2p [NSPLIT * BL * 96];
__device__ float g_dt  [BL * DI];
__device__ float g_y   [BL * DI];
__device__ float g_hq  [B_SZ * NCH * DI * DS];
__device__ float g_hP  [B_SZ * NCH * DI * DS];
__device__ float g_rWin [2 * DI * DM];   // tf32-rounded weights
__device__ float g_rWdt [DI * DTR];
__device__ float g_rWout[DM * DI];

// ---------------- helpers ----------------
__device__ __forceinline__ uint32_t f2tf32(float v)
{
    uint32_t r;
    asm("cvt.rna.tf32.f32 %0, %1;" : "=r"(r) : "f"(v));
    return r;
}
__device__ __forceinline__ float rtf(float v) { return __uint_as_float(f2tf32(v)); }

__device__ __forceinline__ void mma_tf32(float* d, const uint32_t* a, const uint32_t* b)
{
    asm volatile(
        "mma.sync.aligned.m16n8k8.row.col.f32.tf32.tf32.f32 "
        "{%0,%1,%2,%3}, {%4,%5,%6,%7}, {%8,%9}, {%0,%1,%2,%3};\n"
        : "+f"(d[0]), "+f"(d[1]), "+f"(d[2]), "+f"(d[3])
        : "r"(a[0]), "r"(a[1]), "r"(a[2]), "r"(a[3]), "r"(b[0]), "r"(b[1]));
}

__device__ __forceinline__ void cp16(float* smem, const float* g)
{
    uint32_t sa = (uint32_t)__cvta_generic_to_shared(smem);
    asm volatile("cp.async.cg.shared.global [%0], [%1], 16;\n" :: "r"(sa), "l"(g));
}
__device__ __forceinline__ void cp_commit() { asm volatile("cp.async.commit_group;\n"); }
template<int N>
__device__ __forceinline__ void cp_wait() { asm volatile("cp.async.wait_group %0;\n" :: "n"(N)); }

// ---------------- tf32 weight pre-rounding (all three weights, one kernel) ----------------
#define N4_WIN  (2 * DI * DM / 4)
#define N4_WDT  (DI * DTR / 4)
#define N4_WOUT (DM * DI / 4)
__global__ void cvt_all(const float* __restrict__ Win, const float* __restrict__ Wdt,
                        const float* __restrict__ Wout, float* __restrict__ rWin,
                        float* __restrict__ rWdt, float* __restrict__ rWout)
{
    int i = blockIdx.x * 256 + threadIdx.x;
    const float4* src; float4* dst; int j;
    if (i < N4_WIN) { src = (const float4*)Win; dst = (float4*)rWin; j = i; }
    else if (i < N4_WIN + N4_WDT) { src = (const float4*)Wdt; dst = (float4*)rWdt; j = i - N4_WIN; }
    else if (i < N4_WIN + N4_WDT + N4_WOUT) { src = (const float4*)Wout; dst = (float4*)rWout; j = i - N4_WIN - N4_WDT; }
    else return;
    float4 v = src[j];
    v.x = rtf(v.x); v.y = rtf(v.y); v.z = rtf(v.z); v.w = rtf(v.w);
    dst[j] = v;
}

// ---------------- single-pass LayerNorm (tf32-rounded output) ----------------
__global__ void ln_kernel(const float* __restrict__ x, const float* __restrict__ g,
                          const float* __restrict__ b, float* __restrict__ out)
{
    int row = blockIdx.x;
    int t = threadIdx.x;                      // 256 threads, one float4 each
    float4 v = ((const float4*)(x + (size_t)row * DM))[t];
    float s  = v.x + v.y + v.z + v.w;
    float s2 = v.x*v.x + v.y*v.y + v.z*v.z + v.w*v.w;
    __shared__ float sh[18];
    #pragma unroll
    for (int o = 16; o > 0; o >>= 1) {
        s  += __shfl_xor_sync(0xffffffffu, s,  o);
        s2 += __shfl_xor_sync(0xffffffffu, s2, o);
    }
    int wid = t >> 5, lid = t & 31;
    if (lid == 0) { sh[wid] = s; sh[8 + wid] = s2; }
    __syncthreads();
    if (t == 0) {
        float a = 0.f, c = 0.f;
        #pragma unroll
        for (int w = 0; w < 8; w++) { a += sh[w]; c += sh[8 + w]; }
        float mu = a / DM;
        float var = c / DM - mu * mu;
        sh[16] = mu; sh[17] = rsqrtf(var + 1e-5f);
    }
    __syncthreads();
    float mu = sh[16], rs = sh[17];
    float4 gg = ((const float4*)g)[t];
    float4 bb = ((const float4*)b)[t];
    float4 o4;
    o4.x = rtf((v.x - mu) * rs * gg.x + bb.x);
    o4.y = rtf((v.y - mu) * rs * gg.y + bb.y);
    o4.z = rtf((v.z - mu) * rs * gg.z + bb.z);
    o4.w = rtf((v.w - mu) * rs * gg.w + bb.w);
    ((float4*)(out + (size_t)row * DM))[t] = o4;
}

// ---------------- tf32 TC GEMM, 4-stage cp.async pipeline ----------------
template<int EPI>
__global__ void __launch_bounds__(256)
gemm_tf32(const float* __restrict__ A, int lda,
          const float* __restrict__ W,
          const float* __restrict__ bias,
          const float* __restrict__ res,
          float* __restrict__ C, int ldc, int K)
{
    extern __shared__ float smem[];
    float* Abuf = smem;                       // [4][128][LDT]
    float* Wbuf = smem + 4 * 128 * LDT;

    int bm = blockIdx.y * 128, bn = blockIdx.x * 128;
    int t = threadIdx.x;
    int lane = t & 31, wid = t >> 5;
    int gr = lane >> 2, ct = lane & 3;
    int wm = (wid & 3) * 32, wn = (wid >> 2) * 64;

    int c0 = t * 2, c1 = t * 2 + 1;
    int r0 = c0 >> 2, s0 = (c0 & 3) * 4;
    int r1 = c1 >> 2, s1 = (c1 & 3) * 4;

    float acc[2][8][4];
    #pragma unroll
    for (int i = 0; i < 2; i++)
        #pragma unroll
        for (int j = 0; j < 8; j++)
            #pragma unroll
            for (int k = 0; k < 4; k++) acc[i][j][k] = 0.f;

    int nk = K >> 4;

    #define LOAD_STAGE(kt) {                                                   \
        int st_ = (kt) & 3;                                                    \
        float* as_ = Abuf + st_ * (128 * LDT);                                 \
        float* ws_ = Wbuf + st_ * (128 * LDT);                                 \
        cp16(as_ + r0 * LDT + s0, A + (size_t)(bm + r0) * lda + (kt) * 16 + s0); \
        cp16(as_ + r1 * LDT + s1, A + (size_t)(bm + r1) * lda + (kt) * 16 + s1); \
        cp16(ws_ + r0 * LDT + s0, W + (size_t)(bn + r0) * K + (kt) * 16 + s0); \
        cp16(ws_ + r1 * LDT + s1, W + (size_t)(bn + r1) * K + (kt) * 16 + s1); \
    }

    #pragma unroll
    for (int s = 0; s < 3; s++) {
        if (s < nk) LOAD_STAGE(s);
        cp_commit();
    }

    for (int kt = 0; kt < nk; kt++) {
        cp_wait<2>();
        __syncthreads();
        if (kt + 3 < nk) LOAD_STAGE(kt + 3);
        cp_commit();

        const float* as = Abuf + (kt & 3) * (128 * LDT);
        const float* ws = Wbuf + (kt & 3) * (128 * LDT);
        #pragma unroll
        for (int ks = 0; ks < 2; ks++) {
            int kk = ks * 8;
            uint32_t af[2][4], bf[8][2];
            #pragma unroll
            for (int mi = 0; mi < 2; mi++) {
                int mr = wm + mi * 16 + gr;
                af[mi][0] = __float_as_uint(as[(size_t)mr * LDT + kk + ct]);
                af[mi][1] = __float_as_uint(as[(size_t)(mr + 8) * LDT + kk + ct]);
                af[mi][2] = __float_as_uint(as[(size_t)mr * LDT + kk + ct + 4]);
                af[mi][3] = __float_as_uint(as[(size_t)(mr + 8) * LDT + kk + ct + 4]);
            }
            #pragma unroll
            for (int ni = 0; ni < 8; ni++) {
                int nc = wn + ni * 8 + gr;
                bf[ni][0] = __float_as_uint(ws[(size_t)nc * LDT + kk + ct]);
                bf[ni][1] = __float_as_uint(ws[(size_t)nc * LDT + kk + ct + 4]);
            }
            #pragma unroll
            for (int mi = 0; mi < 2; mi++)
                #pragma unroll
                for (int ni = 0; ni < 8; ni++)
                    mma_tf32(acc[mi][ni], af[mi], bf[ni]);
        }
    }
    #undef LOAD_STAGE

    #pragma unroll
    for (int mi = 0; mi < 2; mi++) {
        #pragma unroll
        for (int half = 0; half < 2; half++) {
            int row = bm + wm + mi * 16 + gr + half * 8;
            #pragma unroll
            for (int ni = 0; ni < 8; ni++) {
                int col = bn + wn + ni * 8 + ct * 2;
                float v0 = acc[mi][ni][half * 2 + 0];
                float v1 = acc[mi][ni][half * 2 + 1];
                if (bias) { v0 += bias[col]; v1 += bias[col + 1]; }
                if (EPI == 1) {
                    v0 = (v0 > 20.f) ? v0 : __logf(1.f + __expf(v0));
                    v1 = (v1 > 20.f) ? v1 : __logf(1.f + __expf(v1));
                }
                if (EPI == 2) {
                    const float* rr = res + (size_t)row * ldc;
                    v0 += rr[col]; v1 += rr[col + 1];
                }
                *(float2*)(C + (size_t)row * ldc + col) = make_float2(v0, v1);
            }
        }
    }
}

// ---------------- fused depthwise conv + SiLU + GEMM2 split-K ----------------
__global__ void __launch_bounds__(256)
conv_gemm2(const float* __restrict__ xz, const float* __restrict__ cw,
           const float* __restrict__ cb, const float* __restrict__ W,
           float* __restrict__ xc, float* __restrict__ part)
{
    __shared__ float XC[KC][68];     // [channel][row]
    __shared__ float Ws[16][100];
    int bm = blockIdx.x * 64;
    int ks = blockIdx.y;
    int k0 = ks * KC;
    int t = threadIdx.x;

    {
        int ch = t & 127;
        int rg = t >> 7;               // 0 or 1
        int d  = k0 + ch;
        float w0 = cw[d * 4 + 0], w1 = cw[d * 4 + 1];
        float w2 = cw[d * 4 + 2], w3 = cw[d * 4 + 3];
        float bconv = cb[d];
        int rbeg = rg * 32;
        int bl0 = bm + rbeg;
        int l0  = bl0 & (L_SZ - 1);
        float xm3 = (l0 >= 3) ? xz[(size_t)(bl0 - 3) * (2 * DI) + d] : 0.f;
        float xm2 = (l0 >= 2) ? xz[(size_t)(bl0 - 2) * (2 * DI) + d] : 0.f;
        float xm1 = (l0 >= 1) ? xz[(size_t)(bl0 - 1) * (2 * DI) + d] : 0.f;
        #pragma unroll 4
        for (int r = rbeg; r < rbeg + 32; r++) {
            int bl = bm + r;
            float x0 = xz[(size_t)bl * (2 * DI) + d];
            float acc = bconv;
            acc = fmaf(xm3, w0, acc);
            acc = fmaf(xm2, w1, acc);
            acc = fmaf(xm1, w2, acc);
            acc = fmaf(x0,  w3, acc);
            float v = acc / (1.f + __expf(-acc));
            XC[ch][r] = v;
            xc[(size_t)bl * DI + d] = v;
            xm3 = xm2; xm2 = xm1; xm1 = x0;
        }
    }
    __syncthreads();

    int tr = t >> 4, tc = t & 15;
    float acc[4][6];
    #pragma unroll
    for (int i = 0; i < 4; i++)
        #pragma unroll
        for (int j = 0; j < 6; j++) acc[i][j] = 0.f;

    for (int kk = 0; kk < KC; kk += 16) {
        #pragma unroll
        for (int p = 0; p < 2; p++) {
            int idx = t + p * 256;
            if (idx < 384) {
                int wrow = idx >> 2, wseg = (idx & 3) * 4;
                float4 wv = *(const float4*)(W + (size_t)wrow * DI + k0 + kk + wseg);
                Ws[wseg+0][wrow] = wv.x; Ws[wseg+1][wrow] = wv.y;
                Ws[wseg+2][wrow] = wv.z; Ws[wseg+3][wrow] = wv.w;
            }
        }
        __syncthreads();
        #pragma unroll
        for (int k = 0; k < 16; k++) {
            float ar[4], wr[6];
            #pragma unroll
            for (int i = 0; i < 4; i++) ar[i] = XC[kk + k][tr * 4 + i];
            #pragma unroll
            for (int j = 0; j < 6; j++) wr[j] = Ws[k][tc * 6 + j];
            #pragma unroll
            for (int i = 0; i < 4; i++)
                #pragma unroll
                for (int j = 0; j < 6; j++)
                    acc[i][j] = fmaf(ar[i], wr[j], acc[i][j]);
        }
        __syncthreads();
    }
    #pragma unroll
    for (int i = 0; i < 4; i++)
        #pragma unroll
        for (int j = 0; j < 6; j++)
            part[((size_t)ks * BL + bm + tr * 4 + i) * 96 + tc * 6 + j] = acc[i][j];
}

// reduce + tf32-round the dt_lo columns (0..63) for GEMM5
__global__ void reduce_split(const float* __restrict__ p, float* __restrict__ o)
{
    int i = blockIdx.x * 256 + threadIdx.x;
    if (i < BL * 96) {
        float s = 0.f;
        #pragma unroll
        for (int k = 0; k < NSPLIT; k++) s += p[(size_t)k * BL * 96 + i];
        int col = i % 96;
        o[i] = (col < 64) ? rtf(s) : s;
    }
}

// ---------------- chunked selective scan, 4 lanes/channel x 4 states/lane ----------------
// grid (DI/64, NCH, B_SZ), block 256. Warp covers 8 channels; squad = 4 lanes.
__global__ void __launch_bounds__(256)
scan_pass1(const float* __restrict__ dt, const float* __restrict__ xc,
           const float* __restrict__ xdbl, const float* __restrict__ A_log,
           float* __restrict__ hq, float* __restrict__ hP)
{
    int t = threadIdx.x;
    int lane = t & 31, w = t >> 5;
    int q = lane & 3;                      // state quad: states q*4..q*4+3
    int d = blockIdx.x * 64 + w * 8 + (lane >> 2);
    int c = blockIdx.y;
    int b = blockIdx.z;
    float4 al = *(const float4*)&A_log[d * DS + q * 4];
    float a0 = -__expf(al.x), a1 = -__expf(al.y);
    float a2 = -__expf(al.z), a3 = -__expf(al.w);
    float h0 = 0.f, h1 = 0.f, h2 = 0.f, h3 = 0.f;
    float P0 = 1.f, P1 = 1.f, P2 = 1.f, P3 = 1.f;
    int base = b * L_SZ + c * LC;
    #pragma unroll 4
    for (int l = 0; l < LC; l++) {
        int bl = base + l;
        float dtv = dt[(size_t)bl * DI + d];
        float xcv = xc[(size_t)bl * DI + d];
        float4 B4 = *(const float4*)&xdbl[(size_t)bl * 96 + 64 + q * 4];
        float dx = dtv * xcv;
        float dA0 = __expf(dtv * a0); h0 = fmaf(dA0, h0, dx * B4.x); P0 *= dA0;
        float dA1 = __expf(dtv * a1); h1 = fmaf(dA1, h1, dx * B4.y); P1 *= dA1;
        float dA2 = __expf(dtv * a2); h2 = fmaf(dA2, h2, dx * B4.z); P2 *= dA2;
        float dA3 = __expf(dtv * a3); h3 = fmaf(dA3, h3, dx * B4.w); P3 *= dA3;
    }
    size_t idx = ((size_t)(b * NCH + c) * DI + d) * DS + q * 4;
    *(float4*)&hq[idx] = make_float4(h0, h1, h2, h3);
    *(float4*)&hP[idx] = make_float4(P0, P1, P2, P3);
}

__global__ void __launch_bounds__(256)
scan_pass2(const float* __restrict__ dt, const float* __restrict__ xc,
           const float* __restrict__ xdbl, const float* __restrict__ A_log,
           const float* __restrict__ Dp, const float* __restrict__ xz,
           const float* __restrict__ hq, const float* __restrict__ hP,
           float* __restrict__ y)
{
    int t = threadIdx.x;
    int lane = t & 31, w = t >> 5;
    int q = lane & 3;
    int d = blockIdx.x * 64 + w * 8 + (lane >> 2);
    int c = blockIdx.y;
    int b = blockIdx.z;
    float4 al = *(const float4*)&A_log[d * DS + q * 4];
    float a0 = -__expf(al.x), a1 = -__expf(al.y);
    float a2 = -__expf(al.z), a3 = -__expf(al.w);
    float dscale = Dp[d];
    // inline fixup: h0 = scan of (P,q) over chunks 0..c-1
    float h0 = 0.f, h1 = 0.f, h2 = 0.f, h3 = 0.f;
    for (int cc = 0; cc < c; cc++) {
        size_t idx = ((size_t)(b * NCH + cc) * DI + d) * DS + q * 4;
        float4 q4 = *(const float4*)&hq[idx];
        float4 p4 = *(const float4*)&hP[idx];
        h0 = fmaf(p4.x, h0, q4.x);
        h1 = fmaf(p4.y, h1, q4.y);
        h2 = fmaf(p4.z, h2, q4.z);
        h3 = fmaf(p4.w, h3, q4.w);
    }
    int base = b * L_SZ + c * LC;
    #pragma unroll 4
    for (int l = 0; l < LC; l++) {
        int bl = base + l;
        float dtv = dt[(size_t)bl * DI + d];
        float xcv = xc[(size_t)bl * DI + d];
        float4 B4 = *(const float4*)&xdbl[(size_t)bl * 96 + 64 + q * 4];
        float4 C4 = *(const float4*)&xdbl[(size_t)bl * 96 + 80 + q * 4];
        float dx = dtv * xcv;
        float dA0 = __expf(dtv * a0); h0 = fmaf(dA0, h0, dx * B4.x);
        float dA1 = __expf(dtv * a1); h1 = fmaf(dA1, h1, dx * B4.y);
        float dA2 = __expf(dtv * a2); h2 = fmaf(dA2, h2, dx * B4.z);
        float dA3 = __expf(dtv * a3); h3 = fmaf(dA3, h3, dx * B4.w);
        float yp = h0 * C4.x;
        yp = fmaf(h1, C4.y, yp);
        yp = fmaf(h2, C4.z, yp);
        yp = fmaf(h3, C4.w, yp);
        yp += __shfl_xor_sync(0xffffffffu, yp, 1);
        yp += __shfl_xor_sync(0xffffffffu, yp, 2);
        if (q == 0) {
            float zv = xz[(size_t)bl * (2 * DI) + DI + d];
            float sz = zv / (1.f + __expf(-zv));
            y[(size_t)bl * DI + d] = rtf((yp + dscale * xcv) * sz);
        }
    }
}

// ---------------- host launcher ----------------
extern "C" void kernel_launch(void* const* d_in, const int* in_sizes, int n_in,
                              void* d_out, int out_size)
{
    const float* x      = (const float*)d_in[0];
    const float* ln_g   = (const float*)d_in[1];
    const float* ln_b   = (const float*)d_in[2];
    const float* W_in   = (const float*)d_in[3];
    const float* b_in   = (const float*)d_in[4];
    const float* conv_w = (const float*)d_in[5];
    const float* conv_b = (const float*)d_in[6];
    const float* W_x    = (const float*)d_in[7];
    const float* W_dt   = (const float*)d_in[8];
    const float* b_dt   = (const float*)d_in[9];
    const float* A_log  = (const float*)d_in[10];
    const float* Dv     = (const float*)d_in[11];
    const float* W_out  = (const float*)d_in[12];
    const float* b_out  = (const float*)d_in[13];
    float* out = (float*)d_out;

    float *xn, *xz, *xc, *xdbl, *x2p, *dtb, *yb, *hq, *hP;
    float *rWin, *rWdt, *rWout;
    cudaGetSymbolAddress((void**)&xn,   g_xn);
    cudaGetSymbolAddress((void**)&xz,   g_xz);
    cudaGetSymbolAddress((void**)&xc,   g_xc);
    cudaGetSymbolAddress((void**)&xdbl, g_xdbl);
    cudaGetSymbolAddress((void**)&x2p,  g_x2p);
    cudaGetSymbolAddress((void**)&dtb,  g_dt);
    cudaGetSymbolAddress((void**)&yb,   g_y);
    cudaGetSymbolAddress((void**)&hq,   g_hq);
    cudaGetSymbolAddress((void**)&hP,   g_hP);
    cudaGetSymbolAddress((void**)&rWin, g_rWin);
    cudaGetSymbolAddress((void**)&rWdt, g_rWdt);
    cudaGetSymbolAddress((void**)&rWout,g_rWout);

    static bool attr_done = false;
    if (!attr_done) {
        cudaFuncSetAttribute(gemm_tf32<0>, cudaFuncAttributeMaxDynamicSharedMemorySize, GSM);
        cudaFuncSetAttribute(gemm_tf32<1>, cudaFuncAttributeMaxDynamicSharedMemorySize, GSM);
        cudaFuncSetAttribute(gemm_tf32<2>, cudaFuncAttributeMaxDynamicSharedMemorySize, GSM);
        attr_done = true;
    }

    // 0. pre-round all weights to tf32
    cvt_all<<<(N4_WIN + N4_WDT + N4_WOUT + 255) / 256, 256>>>(
        W_in, W_dt, W_out, rWin, rWdt, rWout);

    // 1. single-pass LayerNorm (tf32-rounded output)
    ln_kernel<<<BL, 256>>>(x, ln_g, ln_b, xn);

    // 2. in-projection (tf32 TC, cp.async pipelined)
    gemm_tf32<0><<<dim3(4096 / 128, BL / 128), 256, GSM>>>(
        xn, DM, rWin, b_in, nullptr, xz, 2 * DI, DM);

    // 3+4. fused conv+SiLU+GEMM2 split-K, then reduce
    conv_gemm2<<<dim3(BL / 64, NSPLIT), 256>>>(xz, conv_w, conv_b, W_x, xc, x2p);
    reduce_split<<<(BL * 96 + 255) / 256, 256>>>(x2p, xdbl);

    // 5. dt = softplus(dt_lo @ W_dt^T + b_dt)
    gemm_tf32<1><<<dim3(DI / 128, BL / 128), 256, GSM>>>(
        xdbl, 96, rWdt, b_dt, nullptr, dtb, DI, DTR);

    // 6. chunked selective scan (4 lanes/channel, vectorized B/C)
    scan_pass1<<<dim3(DI / 64, NCH, B_SZ), 256>>>(dtb, xc, xdbl, A_log, hq, hP);
    scan_pass2<<<dim3(DI / 64, NCH, B_SZ), 256>>>(dtb, xc, xdbl, A_log, Dv, xz, hq, hP, yb);

    // 7. out-projection + residual
    gemm_tf32<2><<<dim3(DM / 128, BL / 128), 256, GSM>>>(
        yb, DI, rWout, b_out, x, out, DM, DI);
}